// round 7
// baseline (speedup 1.0000x reference)
#include <cuda_runtime.h>
#include <cuda_bf16.h>
#include <cstdint>

#define NN 50000
#define NE 800000
#define AF 133
#define BF 14
#define H  128
#define SA_STRIDE 136   // padded bf16 smem row stride (conflict-free LDSM)
#define SD_STRIDE 132   // padded fp32 smem row stride for epilogues
#define BMAT (128 * SA_STRIDE)          // B matrix smem elems (34816 B)
#define AMAT (64 * SA_STRIDE)           // A tile smem elems per matrix (17408 B)
#define ETILE 64
#define TILES_PER_CTA 5
#define EGRID (NE / ETILE / TILES_PER_CTA)   // 2500

// node-gemm tiling (proven R6): K chunks of 144, smem row stride 152
#define NGS  152
#define NGMAT (128 * NGS)
#define NROWS_PAD 50048            // 391 * 128
#define NGRID 391

// ---------------- scratch (device globals; no allocation) ----------------
__device__ float g_y1[(size_t)NE * H];
__device__ float g_y2[(size_t)NE * H];
__device__ float g_P [(size_t)NN * H];
__device__ float g_S1[(size_t)NN * H];
__device__ float g_S2[(size_t)NN * H];
__device__ float g_S3[(size_t)NN * H];
__device__ float g_WbT[BF * H];                    // [k][j], fp32 (edge init)
__device__ __nv_bfloat16 g_Bh[H * H];              // Wh hi  [n][k]
__device__ __nv_bfloat16 g_Bl[H * H];              // Wh lo
__device__ __nv_bfloat16 g_W1h[128 * 144];         // Wa padded, hi  [n][k]
__device__ __nv_bfloat16 g_W1l[128 * 144];
__device__ __nv_bfloat16 g_W2h[128 * 288];         // Wo padded, hi  [n][k]
__device__ __nv_bfloat16 g_W2l[128 * 288];
__device__ __nv_bfloat16 g_A1h[(size_t)NROWS_PAD * 144];   // atom panel hi
__device__ __nv_bfloat16 g_A1l[(size_t)NROWS_PAD * 144];
__device__ __nv_bfloat16 g_A2h[(size_t)NROWS_PAD * 288];   // [atom|S3] panel hi
__device__ __nv_bfloat16 g_A2l[(size_t)NROWS_PAD * 288];
__device__ int   g_idx64;

// ---------------- helpers ----------------
__device__ __forceinline__ int ld_idx(const void* p, long i) {
    if (g_idx64) return (int)__ldg((const long long*)p + i);
    return __ldg((const int*)p + i);
}
__device__ __forceinline__ void red4(float* p, float4 v) {
    asm volatile("red.global.add.v4.f32 [%0], {%1,%2,%3,%4};"
                 :: "l"(p), "f"(v.x), "f"(v.y), "f"(v.z), "f"(v.w) : "memory");
}
__device__ __forceinline__ uint32_t smem_u32(const void* p) {
    uint32_t a;
    asm("{ .reg .u64 t; cvta.to.shared.u64 t, %1; cvt.u32.u64 %0, t; }" : "=r"(a) : "l"(p));
    return a;
}
__device__ __forceinline__ void bsplit(float v, __nv_bfloat16& h, __nv_bfloat16& l) {
    h = __float2bfloat16(v);
    l = __float2bfloat16(v - __bfloat162float(h));
}
__device__ __forceinline__ uint32_t bpack(__nv_bfloat16 a, __nv_bfloat16 b) {
    return ((uint32_t)__bfloat16_as_ushort(b) << 16) | (uint32_t)__bfloat16_as_ushort(a);
}
__device__ __forceinline__ void ldsm_x4(uint32_t (&r)[4], uint32_t addr) {
    asm volatile("ldmatrix.sync.aligned.m8n8.x4.shared.b16 {%0,%1,%2,%3}, [%4];"
                 : "=r"(r[0]), "=r"(r[1]), "=r"(r[2]), "=r"(r[3]) : "r"(addr));
}
__device__ __forceinline__ void ldsm_x2(uint32_t (&r)[2], uint32_t addr) {
    asm volatile("ldmatrix.sync.aligned.m8n8.x2.shared.b16 {%0,%1}, [%2];"
                 : "=r"(r[0]), "=r"(r[1]) : "r"(addr));
}
__device__ __forceinline__ void mma_bf16(float (&d)[4], const uint32_t (&a)[4], const uint32_t (&b)[2]) {
    asm volatile("mma.sync.aligned.m16n8k16.row.col.f32.bf16.bf16.f32 "
                 "{%0,%1,%2,%3}, {%4,%5,%6,%7}, {%8,%9}, {%0,%1,%2,%3};"
                 : "+f"(d[0]), "+f"(d[1]), "+f"(d[2]), "+f"(d[3])
                 : "r"(a[0]), "r"(a[1]), "r"(a[2]), "r"(a[3]), "r"(b[0]), "r"(b[1]));
}

// ======= prep_all: zero S bufs | weight prep | atom panel cvt | idx detect ===
#define ZB 18750                        // 3*NN*H/4 / 256
#define WB 144                          // (128*288+255)/256
#define CB 28152                        // NROWS_PAD*144 / 256
__global__ __launch_bounds__(256) void prep_all(
    const float* __restrict__ Wi, const float* __restrict__ Wh,
    const float* __restrict__ Wo, const float* __restrict__ atom,
    const unsigned int* __restrict__ srcw,
    float4* __restrict__ S1, float4* __restrict__ S2, float4* __restrict__ S3)
{
    int b = blockIdx.x;
    if (b < ZB) {                                   // zero S1,S2,S3
        const long n = (long)NN * H / 4;
        long i = (long)b * 256 + threadIdx.x;
        float4 z = make_float4(0.f, 0.f, 0.f, 0.f);
        if (i < n) S1[i] = z;
        else if (i < 2 * n) S2[i - n] = z;
        else S3[i - 2 * n] = z;
        return;
    }
    b -= ZB;
    if (b < WB) {                                   // weight prep
        int i = b * 256 + threadIdx.x;
        if (i >= 128 * 288) return;
        if (i < BF * H) {
            int j = i & 127, k = i >> 7;
            g_WbT[i] = Wi[j * (AF + BF) + AF + k];
        }
        if (i < H * H) {
            __nv_bfloat16 hi, lo; bsplit(Wh[i], hi, lo);
            g_Bh[i] = hi; g_Bl[i] = lo;
        }
        if (i < 128 * 144) {
            int n = i / 144, k = i % 144;
            float v = (k < AF) ? Wi[n * (AF + BF) + k] : 0.f;
            __nv_bfloat16 hi, lo; bsplit(v, hi, lo);
            g_W1h[i] = hi; g_W1l[i] = lo;
        }
        {
            int n = i / 288, k = i % 288;
            float v = (k < AF + H) ? Wo[n * (AF + H) + k] : 0.f;
            __nv_bfloat16 hi, lo; bsplit(v, hi, lo);
            g_W2h[i] = hi; g_W2l[i] = lo;
        }
        return;
    }
    b -= WB;
    if (b < CB) {                                   // cvt1: atom panel
        long i = (long)b * 256 + threadIdx.x;
        int r = (int)(i / 144), c = (int)(i % 144);
        float v = (r < NN && c < AF) ? __ldg(atom + (size_t)r * AF + c) : 0.f;
        __nv_bfloat16 hi, lo; bsplit(v, hi, lo);
        g_A1h[i] = hi; g_A1l[i] = lo;
        return;
    }
    // detect int32 vs int64
    __shared__ unsigned int s;
    if (threadIdx.x == 0) s = 0;
    __syncthreads();
    unsigned int v = srcw[threadIdx.x * 2 + 1] | srcw[2048 + threadIdx.x * 2 + 1];
    atomicOr(&s, v);
    __syncthreads();
    if (threadIdx.x == 0) g_idx64 = (s == 0u) ? 1 : 0;
}

// ---------------- cvt2: [atom|S3] panel (bf16 hi/lo, padded) -----------------
__global__ void cvt2(const float* __restrict__ atom, const float* __restrict__ S3) {
    long i = (long)blockIdx.x * blockDim.x + threadIdx.x;
    if (i >= (long)NROWS_PAD * 288) return;
    int r = (int)(i / 288), c = (int)(i % 288);
    float v = 0.f;
    if (r < NN) {
        if (c < AF) v = __ldg(atom + (size_t)r * AF + c);
        else if (c < AF + H) v = __ldg(S3 + (size_t)r * H + (c - AF));
    }
    __nv_bfloat16 hi, lo; bsplit(v, hi, lo);
    g_A2h[i] = hi; g_A2l[i] = lo;
}

// ---------------- node GEMM via mma.sync (proven R6) -------------------------
template<int KPAD, bool RELU>
__global__ __launch_bounds__(512, 1) void ngemm(
    const __nv_bfloat16* __restrict__ Ahg, const __nv_bfloat16* __restrict__ Alg,
    const __nv_bfloat16* __restrict__ Whg, const __nv_bfloat16* __restrict__ Wlg,
    float* __restrict__ out)
{
    extern __shared__ __align__(16) char dyn[];
    __nv_bfloat16* sBh = (__nv_bfloat16*)dyn;
    __nv_bfloat16* sBl = sBh + NGMAT;
    __nv_bfloat16* sAh = sBl + NGMAT;
    __nv_bfloat16* sAl = sAh + NGMAT;

    int tid = threadIdx.x, lane = tid & 31, wid = tid >> 5;
    int m0 = blockIdx.x * 128;
    int wm = (wid >> 2) * 32, wn = (wid & 3) * 32;

    float acc[2][4][4];
    #pragma unroll
    for (int mt = 0; mt < 2; mt++)
        #pragma unroll
        for (int nt = 0; nt < 4; nt++)
            #pragma unroll
            for (int i = 0; i < 4; i++) acc[mt][nt][i] = 0.f;

    const int NCH = KPAD / 144;
    #pragma unroll
    for (int ch = 0; ch < NCH; ch++) {
        if (ch) __syncthreads();
        for (int i = tid; i < 128 * 18; i += 512) {
            int r = i / 18, c = i % 18;
            int go = r * KPAD + ch * 144 + c * 8;
            *(uint4*)(sBh + r * NGS + c * 8) = *(const uint4*)(Whg + go);
            *(uint4*)(sBl + r * NGS + c * 8) = *(const uint4*)(Wlg + go);
        }
        for (int i = tid; i < 128 * 18; i += 512) {
            int r = i / 18, c = i % 18;
            size_t go = (size_t)(m0 + r) * KPAD + ch * 144 + c * 8;
            *(uint4*)(sAh + r * NGS + c * 8) = *(const uint4*)(Ahg + go);
            *(uint4*)(sAl + r * NGS + c * 8) = *(const uint4*)(Alg + go);
        }
        __syncthreads();

        #pragma unroll
        for (int pass = 0; pass < 3; pass++) {
            uint32_t abase = smem_u32(pass == 1 ? sAl : sAh);
            uint32_t bbase = smem_u32(pass == 2 ? sBl : sBh);
            uint32_t aAddr0 = abase + ((uint32_t)(wm + (lane & 15)) * NGS + (lane >> 4) * 8) * 2;
            uint32_t aAddr1 = aAddr0 + 16 * NGS * 2;
            uint32_t bAddr  = bbase + ((uint32_t)(wn + (lane & 7)) * NGS + ((lane >> 3) & 1) * 8) * 2;
            #pragma unroll
            for (int ks = 0; ks < 9; ks++) {
                uint32_t koff = (uint32_t)ks * 32;
                uint32_t a0[4], a1[4];
                ldsm_x4(a0, aAddr0 + koff);
                ldsm_x4(a1, aAddr1 + koff);
                uint32_t b[4][2];
                #pragma unroll
                for (int nt = 0; nt < 4; nt++)
                    ldsm_x2(b[nt], bAddr + (uint32_t)nt * 8 * NGS * 2 + koff);
                #pragma unroll
                for (int nt = 0; nt < 4; nt++) {
                    mma_bf16(acc[0][nt], a0, b[nt]);
                    mma_bf16(acc[1][nt], a1, b[nt]);
                }
            }
        }
    }
    __syncthreads();

    float* sD = (float*)sAh;
    {
        int g = lane >> 2, t2 = (lane & 3) * 2;
        #pragma unroll
        for (int mt = 0; mt < 2; mt++)
            #pragma unroll
            for (int nt = 0; nt < 4; nt++) {
                int r0 = wm + mt * 16 + g, c0 = wn + nt * 8 + t2;
                float2 v0 = make_float2(acc[mt][nt][0], acc[mt][nt][1]);
                float2 v1 = make_float2(acc[mt][nt][2], acc[mt][nt][3]);
                if (RELU) {
                    v0.x = fmaxf(v0.x, 0.f); v0.y = fmaxf(v0.y, 0.f);
                    v1.x = fmaxf(v1.x, 0.f); v1.y = fmaxf(v1.y, 0.f);
                }
                *(float2*)(sD + r0 * SD_STRIDE + c0)       = v0;
                *(float2*)(sD + (r0 + 8) * SD_STRIDE + c0) = v1;
            }
    }
    __syncthreads();
    {
        int row = tid & 127, q = tid >> 7;
        if (m0 + row < NN) {
            const float4* sp = (const float4*)(sD + row * SD_STRIDE + q * 32);
            float* orow = out + (size_t)(m0 + row) * H + q * 32;
            #pragma unroll
            for (int i = 0; i < 8; i++) *(float4*)(orow + i * 4) = sp[i];
        }
    }
}

// ---------------- edge GEMM: 64-row tiles, 256 thr, 2 CTAs/SM ----------------
// MODE 2: A = relu(P[src] + bond @ WbT)   (initial edge layer fused in)
// MODE 1: A = relu(Sprev[src] - Yprev[rev])
// Then Y = A @ Wh^T (3-pass bf16 hi/lo), epilogue: write Y + red-scatter S[dst].
template<int MODE>
__global__ __launch_bounds__(256, 2) void egemm(
    const float* __restrict__ Sprev, const float* __restrict__ Yprev,
    const float* __restrict__ Pn,   const float* __restrict__ bond,
    const void* __restrict__ srcp,  const void* __restrict__ revp,
    const uint4* __restrict__ Bh4,  const uint4* __restrict__ Bl4,
    float* __restrict__ Yout, float* __restrict__ Sout,
    const void* __restrict__ dstp)
{
    extern __shared__ __align__(16) char dyn[];
    __nv_bfloat16* sBh = (__nv_bfloat16*)dyn;                 // 128 x NGS-like B
    __nv_bfloat16* sBl = sBh + BMAT;
    __nv_bfloat16* sAh = sBl + BMAT;                          // 64-row A tile
    __nv_bfloat16* sAl = sAh + AMAT;
    float* sWb = (float*)(sAl + AMAT);                        // MODE2 only: 14x128 fp32

    int tid = threadIdx.x, lane = tid & 31, wid = tid >> 5;

    // B (hi/lo) resident per CTA
    #pragma unroll
    for (int it = 0; it < 8; it++) {
        int i = tid + it * 256;                 // 2048 x 16B per matrix
        int r = i >> 4, c = i & 15;
        *(uint4*)(sBh + r * SA_STRIDE + c * 8) = __ldg(Bh4 + i);
        *(uint4*)(sBl + r * SA_STRIDE + c * 8) = __ldg(Bl4 + i);
    }
    if (MODE == 2) {
        for (int i = tid; i < BF * H; i += 256) sWb[i] = g_WbT[i];
    }

    long tile0 = (long)blockIdx.x * TILES_PER_CTA;
    int wm = (wid >> 2) * 32;          // {0, 32}
    int wn = (wid & 3) * 32;
    __syncthreads();

    for (int t = 0; t < TILES_PER_CTA; t++) {
        long e0 = (tile0 + t) * ETILE;

        // ---- build A rows: thread: row tid>>2 (0..63), 32-col chunk tid&3
        {
            int row = tid >> 2, q = tid & 3;
            long e = e0 + row;
            uint2* dh = (uint2*)(sAh + row * SA_STRIDE + q * 32);
            uint2* dl = (uint2*)(sAl + row * SA_STRIDE + q * 32);
            float4 hv[8];
            if (MODE == 2) {
                int s = ld_idx(srcp, e);
                const float4* pp = (const float4*)(Pn + (size_t)s * H + q * 32);
                float bb[BF];
                const float* br = bond + e * BF;
                #pragma unroll
                for (int k = 0; k < BF; k++) bb[k] = __ldg(br + k);
                #pragma unroll
                for (int i = 0; i < 8; i++) {
                    float4 a = __ldg(pp + i);
                    #pragma unroll
                    for (int k = 0; k < BF; k++) {
                        float4 w = *(const float4*)(sWb + k * H + q * 32 + i * 4);
                        a.x += bb[k] * w.x; a.y += bb[k] * w.y;
                        a.z += bb[k] * w.z; a.w += bb[k] * w.w;
                    }
                    hv[i] = a;
                }
            } else {
                int  s = ld_idx(srcp, e);
                long r = ld_idx(revp, e);
                const float4* ps = (const float4*)(Sprev + (size_t)s * H + q * 32);
                const float4* py = (const float4*)(Yprev + (size_t)r * H + q * 32);
                #pragma unroll
                for (int i = 0; i < 8; i++) {
                    float4 sv = __ldg(ps + i), yv = __ldg(py + i);
                    hv[i] = make_float4(sv.x - yv.x, sv.y - yv.y, sv.z - yv.z, sv.w - yv.w);
                }
            }
            #pragma unroll
            for (int i = 0; i < 8; i++) {
                float4 a = hv[i];
                a.x = fmaxf(a.x, 0.f); a.y = fmaxf(a.y, 0.f);
                a.z = fmaxf(a.z, 0.f); a.w = fmaxf(a.w, 0.f);
                __nv_bfloat16 h0,h1,h2,h3,l0,l1,l2,l3;
                bsplit(a.x,h0,l0); bsplit(a.y,h1,l1); bsplit(a.z,h2,l2); bsplit(a.w,h3,l3);
                dh[i] = make_uint2(bpack(h0,h1), bpack(h2,h3));
                dl[i] = make_uint2(bpack(l0,l1), bpack(l2,l3));
            }
        }
        __syncthreads();

        // ---- mainloop: 3 passes x 8 ksteps; warp grid 2m x 4n, tile 32x32
        float acc[2][4][4];
        #pragma unroll
        for (int mt = 0; mt < 2; mt++)
            #pragma unroll
            for (int nt = 0; nt < 4; nt++)
                #pragma unroll
                for (int i = 0; i < 4; i++) acc[mt][nt][i] = 0.f;

        #pragma unroll
        for (int pass = 0; pass < 3; pass++) {
            uint32_t abase = smem_u32(pass == 1 ? sAl : sAh);
            uint32_t bbase = smem_u32(pass == 2 ? sBl : sBh);
            uint32_t aAddr0 = abase + ((uint32_t)(wm + (lane & 15)) * SA_STRIDE + (lane >> 4) * 8) * 2;
            uint32_t aAddr1 = aAddr0 + 16 * SA_STRIDE * 2;
            uint32_t bAddr  = bbase + ((uint32_t)(wn + (lane & 7)) * SA_STRIDE + ((lane >> 3) & 1) * 8) * 2;
            #pragma unroll
            for (int ks = 0; ks < 8; ks++) {
                uint32_t koff = (uint32_t)ks * 32;
                uint32_t a0[4], a1[4];
                ldsm_x4(a0, aAddr0 + koff);
                ldsm_x4(a1, aAddr1 + koff);
                uint32_t b[4][2];
                #pragma unroll
                for (int nt = 0; nt < 4; nt++)
                    ldsm_x2(b[nt], bAddr + (uint32_t)nt * 8 * SA_STRIDE * 2 + koff);
                #pragma unroll
                for (int nt = 0; nt < 4; nt++) {
                    mma_bf16(acc[0][nt], a0, b[nt]);
                    mma_bf16(acc[1][nt], a1, b[nt]);
                }
            }
        }
        __syncthreads();

        // ---- D fragments -> smem fp32 (overlays A stage: 33792B <= 34816B)
        float* sD = (float*)sAh;
        {
            int g = lane >> 2, t2 = (lane & 3) * 2;
            #pragma unroll
            for (int mt = 0; mt < 2; mt++)
                #pragma unroll
                for (int nt = 0; nt < 4; nt++) {
                    int r0 = wm + mt * 16 + g, c0 = wn + nt * 8 + t2;
                    *(float2*)(sD + r0 * SD_STRIDE + c0)       = make_float2(acc[mt][nt][0], acc[mt][nt][1]);
                    *(float2*)(sD + (r0 + 8) * SD_STRIDE + c0) = make_float2(acc[mt][nt][2], acc[mt][nt][3]);
                }
        }
        __syncthreads();

        // ---- epilogue: thread: row tid&63, 32-col chunk tid>>6
        {
            int row = tid & 63, q = tid >> 6;
            long e = e0 + row;
            int d = ld_idx(dstp, e);
            const float4* sp = (const float4*)(sD + row * SD_STRIDE + q * 32);
            float* yrow = Yout + (size_t)e * H + q * 32;
            float* srow = Sout + (size_t)d * H + q * 32;
            #pragma unroll
            for (int i = 0; i < 8; i++) {
                float4 v = sp[i];
                *(float4*)(yrow + i * 4) = v;
                red4(srow + i * 4, v);
            }
        }
        __syncthreads();
    }
}

// ------- final combine: scatter relu(S2[src] - Y2[rev]) into S3[dst] --------
__global__ __launch_bounds__(256) void combine2(const float* __restrict__ S,
                                                const float* __restrict__ Yv,
                                                const void* __restrict__ src,
                                                const void* __restrict__ rev,
                                                float* __restrict__ S3,
                                                const void* __restrict__ dst) {
    long g = (long)blockIdx.x * 256 + threadIdx.x;
    long e = g >> 5;
    if (e >= NE) return;
    int q = (int)(g & 31) * 4;
    int s = ld_idx(src, e);
    long r = ld_idx(rev, e);
    int d = ld_idx(dst, e);
    float4 sv = *(const float4*)(S + (size_t)s * H + q);
    float4 yv = *(const float4*)(Yv + (size_t)r * H + q);
    float4 h;
    h.x = fmaxf(sv.x - yv.x, 0.f);
    h.y = fmaxf(sv.y - yv.y, 0.f);
    h.z = fmaxf(sv.z - yv.z, 0.f);
    h.w = fmaxf(sv.w - yv.w, 0.f);
    red4(S3 + (size_t)d * H + q, h);
}

// ---------------- launcher ----------------
extern "C" void kernel_launch(void* const* d_in, const int* in_sizes, int n_in,
                              void* d_out, int out_size) {
    const float* atom = (const float*)d_in[0];
    const float* bond = (const float*)d_in[1];
    const float* Wi   = (const float*)d_in[2];
    const float* Wh   = (const float*)d_in[3];
    const float* Wo   = (const float*)d_in[4];
    const void*  src  = d_in[5];
    const void*  dst  = d_in[6];
    const void*  rev  = d_in[7];
    float* out = (float*)d_out;

    __nv_bfloat16 *Bh, *Bl, *W1h, *W1l, *W2h, *W2l, *A1h, *A1l, *A2h, *A2l;
    float *y1, *y2, *P, *S1, *S2, *S3;
    cudaGetSymbolAddress((void**)&Bh, g_Bh);
    cudaGetSymbolAddress((void**)&Bl, g_Bl);
    cudaGetSymbolAddress((void**)&W1h, g_W1h);
    cudaGetSymbolAddress((void**)&W1l, g_W1l);
    cudaGetSymbolAddress((void**)&W2h, g_W2h);
    cudaGetSymbolAddress((void**)&W2l, g_W2l);
    cudaGetSymbolAddress((void**)&A1h, g_A1h);
    cudaGetSymbolAddress((void**)&A1l, g_A1l);
    cudaGetSymbolAddress((void**)&A2h, g_A2h);
    cudaGetSymbolAddress((void**)&A2l, g_A2l);
    cudaGetSymbolAddress((void**)&y1, g_y1);
    cudaGetSymbolAddress((void**)&y2, g_y2);
    cudaGetSymbolAddress((void**)&P,  g_P);
    cudaGetSymbolAddress((void**)&S1, g_S1);
    cudaGetSymbolAddress((void**)&S2, g_S2);
    cudaGetSymbolAddress((void**)&S3, g_S3);

    const int smemN  = 4 * NGMAT * 2;                       // 155648 B
    const int smemE1 = (2 * BMAT + 2 * AMAT) * 2;           // 104448 B
    const int smemE2 = smemE1 + BF * H * 4;                 // 111616 B
    cudaFuncSetAttribute(ngemm<144, false>, cudaFuncAttributeMaxDynamicSharedMemorySize, smemN);
    cudaFuncSetAttribute(ngemm<288, true>,  cudaFuncAttributeMaxDynamicSharedMemorySize, smemN);
    cudaFuncSetAttribute(egemm<1>, cudaFuncAttributeMaxDynamicSharedMemorySize, smemE1);
    cudaFuncSetAttribute(egemm<2>, cudaFuncAttributeMaxDynamicSharedMemorySize, smemE2);

    // 1: prep (zeros + weights + atom panel + idx detect)
    prep_all<<<ZB + WB + CB + 1, 256>>>(Wi, Wh, Wo, atom, (const unsigned int*)src,
                                        (float4*)S1, (float4*)S2, (float4*)S3);
    // 2: P = atom @ Wa^T
    ngemm<144, false><<<NGRID, 512, smemN>>>(A1h, A1l, W1h, W1l, P);
    // 3: iter 1 (initial edge layer fused): A=relu(P[src]+bond@WbT); Y1, S1
    egemm<2><<<EGRID, 256, smemE2>>>(nullptr, nullptr, P, bond, src, nullptr,
                                     (const uint4*)Bh, (const uint4*)Bl, y1, S1, dst);
    // 4: iter 2: A=relu(S1[src]-Y1[rev]); Y2, S2   (ncu capture slot)
    egemm<1><<<EGRID, 256, smemE1>>>(S1, y1, nullptr, nullptr, src, rev,
                                     (const uint4*)Bh, (const uint4*)Bl, y2, S2, dst);
    // 5: scatter relu(S2[src]-Y2[rev]) into S3
    combine2<<<NE * 32 / 256, 256>>>(S2, y2, src, rev, S3, dst);
    // 6: [atom|S3] panel
    cvt2<<<(int)(((long)NROWS_PAD * 288 + 511) / 512), 512>>>(atom, S3);
    // 7: out = relu([atom|S3] @ Wo^T)
    ngemm<288, true><<<NGRID, 512, smemN>>>(A2h, A2l, W2h, W2l, out);
}

// round 8
// speedup vs baseline: 1.0436x; 1.0436x over previous
#include <cuda_runtime.h>
#include <cuda_bf16.h>
#include <cstdint>

#define NN 50000
#define NE 800000
#define AF 133
#define BF 14
#define H  128
#define SA_STRIDE 136   // padded bf16 smem row stride (conflict-free LDSM)
#define SD_STRIDE 132   // padded fp32 smem row stride for epilogues
#define BMAT (128 * SA_STRIDE)          // smem elems per 128x128 bf16 matrix (34816 B)
#define ETILE 128
#define TILES_PER_CTA 5
#define EGRID (NE / ETILE / TILES_PER_CTA)   // 1250

// Y staging layout: per row 4 chunks of 36 words (8 float4 + pad), row stride 148 words
#define SYROW 148
#define SYW(row, q, m) ((row) * SYROW + (q) * 36 + (m) * 4)

// node-gemm tiling (proven R6): K chunks of 144, smem row stride 152
#define NGS  152
#define NGMAT (128 * NGS)
#define NROWS_PAD 50048            // 391 * 128
#define NGRID 391

// ---------------- scratch (device globals; no allocation) ----------------
__device__ float g_y1[(size_t)NE * H];
__device__ float g_y2[(size_t)NE * H];
__device__ float g_P [(size_t)NN * H];
__device__ float g_S1[(size_t)NN * H];
__device__ float g_S2[(size_t)NN * H];
__device__ float g_S3[(size_t)NN * H];
__device__ float g_WbT[BF * H];                    // [k][j], fp32 (edge init)
__device__ __nv_bfloat16 g_Bh[H * H];              // Wh hi  [n][k]
__device__ __nv_bfloat16 g_Bl[H * H];              // Wh lo
__device__ __nv_bfloat16 g_W1h[128 * 144];         // Wa padded, hi  [n][k]
__device__ __nv_bfloat16 g_W1l[128 * 144];
__device__ __nv_bfloat16 g_W2h[128 * 288];         // Wo padded, hi  [n][k]
__device__ __nv_bfloat16 g_W2l[128 * 288];
__device__ __nv_bfloat16 g_A1h[(size_t)NROWS_PAD * 144];   // atom panel hi
__device__ __nv_bfloat16 g_A1l[(size_t)NROWS_PAD * 144];
__device__ __nv_bfloat16 g_A2h[(size_t)NROWS_PAD * 288];   // [atom|S3] panel hi
__device__ __nv_bfloat16 g_A2l[(size_t)NROWS_PAD * 288];
__device__ int   g_idx64;

// ---------------- helpers ----------------
__device__ __forceinline__ int ld_idx(const void* p, long i) {
    if (g_idx64) return (int)__ldg((const long long*)p + i);
    return __ldg((const int*)p + i);
}
__device__ __forceinline__ void red4(float* p, float4 v) {
    asm volatile("red.global.add.v4.f32 [%0], {%1,%2,%3,%4};"
                 :: "l"(p), "f"(v.x), "f"(v.y), "f"(v.z), "f"(v.w) : "memory");
}
__device__ __forceinline__ uint32_t smem_u32(const void* p) {
    uint32_t a;
    asm("{ .reg .u64 t; cvta.to.shared.u64 t, %1; cvt.u32.u64 %0, t; }" : "=r"(a) : "l"(p));
    return a;
}
__device__ __forceinline__ void cp_async16(uint32_t sdst, const void* gsrc) {
    asm volatile("cp.async.cg.shared.global [%0], [%1], 16;" :: "r"(sdst), "l"(gsrc) : "memory");
}
__device__ __forceinline__ void cp_commit() {
    asm volatile("cp.async.commit_group;" ::: "memory");
}
template<int N> __device__ __forceinline__ void cp_wait() {
    asm volatile("cp.async.wait_group %0;" :: "n"(N) : "memory");
}
__device__ __forceinline__ void bsplit(float v, __nv_bfloat16& h, __nv_bfloat16& l) {
    h = __float2bfloat16(v);
    l = __float2bfloat16(v - __bfloat162float(h));
}
__device__ __forceinline__ uint32_t bpack(__nv_bfloat16 a, __nv_bfloat16 b) {
    return ((uint32_t)__bfloat16_as_ushort(b) << 16) | (uint32_t)__bfloat16_as_ushort(a);
}
__device__ __forceinline__ void ldsm_x4(uint32_t (&r)[4], uint32_t addr) {
    asm volatile("ldmatrix.sync.aligned.m8n8.x4.shared.b16 {%0,%1,%2,%3}, [%4];"
                 : "=r"(r[0]), "=r"(r[1]), "=r"(r[2]), "=r"(r[3]) : "r"(addr));
}
__device__ __forceinline__ void ldsm_x2(uint32_t (&r)[2], uint32_t addr) {
    asm volatile("ldmatrix.sync.aligned.m8n8.x2.shared.b16 {%0,%1}, [%2];"
                 : "=r"(r[0]), "=r"(r[1]) : "r"(addr));
}
__device__ __forceinline__ void mma_bf16(float (&d)[4], const uint32_t (&a)[4], const uint32_t (&b)[2]) {
    asm volatile("mma.sync.aligned.m16n8k16.row.col.f32.bf16.bf16.f32 "
                 "{%0,%1,%2,%3}, {%4,%5,%6,%7}, {%8,%9}, {%0,%1,%2,%3};"
                 : "+f"(d[0]), "+f"(d[1]), "+f"(d[2]), "+f"(d[3])
                 : "r"(a[0]), "r"(a[1]), "r"(a[2]), "r"(a[3]), "r"(b[0]), "r"(b[1]));
}

// ======= prep_all: zero S bufs | weight prep | atom panel cvt | idx detect ===
#define ZB 18750                        // 3*NN*H/4 / 256
#define WB 144                          // (128*288+255)/256
#define CB 28152                        // NROWS_PAD*144 / 256
__global__ __launch_bounds__(256) void prep_all(
    const float* __restrict__ Wi, const float* __restrict__ Wh,
    const float* __restrict__ Wo, const float* __restrict__ atom,
    const unsigned int* __restrict__ srcw,
    float4* __restrict__ S1, float4* __restrict__ S2, float4* __restrict__ S3)
{
    int b = blockIdx.x;
    if (b < ZB) {
        const long n = (long)NN * H / 4;
        long i = (long)b * 256 + threadIdx.x;
        float4 z = make_float4(0.f, 0.f, 0.f, 0.f);
        if (i < n) S1[i] = z;
        else if (i < 2 * n) S2[i - n] = z;
        else S3[i - 2 * n] = z;
        return;
    }
    b -= ZB;
    if (b < WB) {
        int i = b * 256 + threadIdx.x;
        if (i >= 128 * 288) return;
        if (i < BF * H) {
            int j = i & 127, k = i >> 7;
            g_WbT[i] = Wi[j * (AF + BF) + AF + k];
        }
        if (i < H * H) {
            __nv_bfloat16 hi, lo; bsplit(Wh[i], hi, lo);
            g_Bh[i] = hi; g_Bl[i] = lo;
        }
        if (i < 128 * 144) {
            int n = i / 144, k = i % 144;
            float v = (k < AF) ? Wi[n * (AF + BF) + k] : 0.f;
            __nv_bfloat16 hi, lo; bsplit(v, hi, lo);
            g_W1h[i] = hi; g_W1l[i] = lo;
        }
        {
            int n = i / 288, k = i % 288;
            float v = (k < AF + H) ? Wo[n * (AF + H) + k] : 0.f;
            __nv_bfloat16 hi, lo; bsplit(v, hi, lo);
            g_W2h[i] = hi; g_W2l[i] = lo;
        }
        return;
    }
    b -= WB;
    if (b < CB) {
        long i = (long)b * 256 + threadIdx.x;
        int r = (int)(i / 144), c = (int)(i % 144);
        float v = (r < NN && c < AF) ? __ldg(atom + (size_t)r * AF + c) : 0.f;
        __nv_bfloat16 hi, lo; bsplit(v, hi, lo);
        g_A1h[i] = hi; g_A1l[i] = lo;
        return;
    }
    __shared__ unsigned int s;
    if (threadIdx.x == 0) s = 0;
    __syncthreads();
    unsigned int v = srcw[threadIdx.x * 2 + 1] | srcw[2048 + threadIdx.x * 2 + 1];
    atomicOr(&s, v);
    __syncthreads();
    if (threadIdx.x == 0) g_idx64 = (s == 0u) ? 1 : 0;
}

// ---------------- cvt2: [atom|S3] panel (bf16 hi/lo, padded) -----------------
__global__ void cvt2(const float* __restrict__ atom, const float* __restrict__ S3) {
    long i = (long)blockIdx.x * blockDim.x + threadIdx.x;
    if (i >= (long)NROWS_PAD * 288) return;
    int r = (int)(i / 288), c = (int)(i % 288);
    float v = 0.f;
    if (r < NN) {
        if (c < AF) v = __ldg(atom + (size_t)r * AF + c);
        else if (c < AF + H) v = __ldg(S3 + (size_t)r * H + (c - AF));
    }
    __nv_bfloat16 hi, lo; bsplit(v, hi, lo);
    g_A2h[i] = hi; g_A2l[i] = lo;
}

// ---------------- node GEMM via mma.sync (proven R6) -------------------------
template<int KPAD, bool RELU>
__global__ __launch_bounds__(512, 1) void ngemm(
    const __nv_bfloat16* __restrict__ Ahg, const __nv_bfloat16* __restrict__ Alg,
    const __nv_bfloat16* __restrict__ Whg, const __nv_bfloat16* __restrict__ Wlg,
    float* __restrict__ out)
{
    extern __shared__ __align__(16) char dyn[];
    __nv_bfloat16* sBh = (__nv_bfloat16*)dyn;
    __nv_bfloat16* sBl = sBh + NGMAT;
    __nv_bfloat16* sAh = sBl + NGMAT;
    __nv_bfloat16* sAl = sAh + NGMAT;

    int tid = threadIdx.x, lane = tid & 31, wid = tid >> 5;
    int m0 = blockIdx.x * 128;
    int wm = (wid >> 2) * 32, wn = (wid & 3) * 32;

    float acc[2][4][4];
    #pragma unroll
    for (int mt = 0; mt < 2; mt++)
        #pragma unroll
        for (int nt = 0; nt < 4; nt++)
            #pragma unroll
            for (int i = 0; i < 4; i++) acc[mt][nt][i] = 0.f;

    const int NCH = KPAD / 144;
    #pragma unroll
    for (int ch = 0; ch < NCH; ch++) {
        if (ch) __syncthreads();
        for (int i = tid; i < 128 * 18; i += 512) {
            int r = i / 18, c = i % 18;
            int go = r * KPAD + ch * 144 + c * 8;
            *(uint4*)(sBh + r * NGS + c * 8) = *(const uint4*)(Whg + go);
            *(uint4*)(sBl + r * NGS + c * 8) = *(const uint4*)(Wlg + go);
        }
        for (int i = tid; i < 128 * 18; i += 512) {
            int r = i / 18, c = i % 18;
            size_t go = (size_t)(m0 + r) * KPAD + ch * 144 + c * 8;
            *(uint4*)(sAh + r * NGS + c * 8) = *(const uint4*)(Ahg + go);
            *(uint4*)(sAl + r * NGS + c * 8) = *(const uint4*)(Alg + go);
        }
        __syncthreads();

        #pragma unroll
        for (int pass = 0; pass < 3; pass++) {
            uint32_t abase = smem_u32(pass == 1 ? sAl : sAh);
            uint32_t bbase = smem_u32(pass == 2 ? sBl : sBh);
            uint32_t aAddr0 = abase + ((uint32_t)(wm + (lane & 15)) * NGS + (lane >> 4) * 8) * 2;
            uint32_t aAddr1 = aAddr0 + 16 * NGS * 2;
            uint32_t bAddr  = bbase + ((uint32_t)(wn + (lane & 7)) * NGS + ((lane >> 3) & 1) * 8) * 2;
            #pragma unroll
            for (int ks = 0; ks < 9; ks++) {
                uint32_t koff = (uint32_t)ks * 32;
                uint32_t a0[4], a1[4];
                ldsm_x4(a0, aAddr0 + koff);
                ldsm_x4(a1, aAddr1 + koff);
                uint32_t b[4][2];
                #pragma unroll
                for (int nt = 0; nt < 4; nt++)
                    ldsm_x2(b[nt], bAddr + (uint32_t)nt * 8 * NGS * 2 + koff);
                #pragma unroll
                for (int nt = 0; nt < 4; nt++) {
                    mma_bf16(acc[0][nt], a0, b[nt]);
                    mma_bf16(acc[1][nt], a1, b[nt]);
                }
            }
        }
    }
    __syncthreads();

    float* sD = (float*)sAh;
    {
        int g = lane >> 2, t2 = (lane & 3) * 2;
        #pragma unroll
        for (int mt = 0; mt < 2; mt++)
            #pragma unroll
            for (int nt = 0; nt < 4; nt++) {
                int r0 = wm + mt * 16 + g, c0 = wn + nt * 8 + t2;
                float2 v0 = make_float2(acc[mt][nt][0], acc[mt][nt][1]);
                float2 v1 = make_float2(acc[mt][nt][2], acc[mt][nt][3]);
                if (RELU) {
                    v0.x = fmaxf(v0.x, 0.f); v0.y = fmaxf(v0.y, 0.f);
                    v1.x = fmaxf(v1.x, 0.f); v1.y = fmaxf(v1.y, 0.f);
                }
                *(float2*)(sD + r0 * SD_STRIDE + c0)       = v0;
                *(float2*)(sD + (r0 + 8) * SD_STRIDE + c0) = v1;
            }
    }
    __syncthreads();
    {
        int row = tid & 127, q = tid >> 7;
        if (m0 + row < NN) {
            const float4* sp = (const float4*)(sD + row * SD_STRIDE + q * 32);
            float* orow = out + (size_t)(m0 + row) * H + q * 32;
            #pragma unroll
            for (int i = 0; i < 8; i++) *(float4*)(orow + i * 4) = sp[i];
        }
    }
}

// ---------------- edge GEMM: 128-row tiles, 512 thr, persistent --------------
// MODE 2: A = relu(P[src] + bond @ WbT)   (initial edge layer fused in)
// MODE 1: A = relu(Sprev[src] - Yprev[rev]); Yprev rows staged via cp.async
//         prefetch (issued during previous tile's mainloop).
// Mainloop: fused k-step (each A/B fragment loaded once, 3 mma passes).
// Epilogue: Y write + red.add.v4 scatter into Sout[dst].
template<int MODE>
__global__ __launch_bounds__(512, 1) void egemm(
    const float* __restrict__ Sprev, const float* __restrict__ Yprev,
    const float* __restrict__ Pn,   const float* __restrict__ bond,
    const void* __restrict__ srcp,  const void* __restrict__ revp,
    const uint4* __restrict__ Bh4,  const uint4* __restrict__ Bl4,
    float* __restrict__ Yout, float* __restrict__ Sout,
    const void* __restrict__ dstp)
{
    extern __shared__ __align__(16) char dyn[];
    __nv_bfloat16* sBh = (__nv_bfloat16*)dyn;
    __nv_bfloat16* sBl = sBh + BMAT;
    __nv_bfloat16* sAh = sBl + BMAT;
    __nv_bfloat16* sAl = sAh + BMAT;
    float* sY  = (float*)(sAl + BMAT);            // MODE1: staged Y rows
    float* sWb = (float*)(sAl + BMAT);            // MODE2: 14x128 fp32

    int tid = threadIdx.x, lane = tid & 31, wid = tid >> 5;
    long tile0 = (long)blockIdx.x * TILES_PER_CTA;
    uint32_t sYb = smem_u32(sY);

    // MODE1: kick off stage(t=0) first so the DRAM fetch overlaps B loading
    if (MODE == 1) {
        long e0s = tile0 * ETILE;
        #pragma unroll
        for (int j = 0; j < 8; j++) {
            int c = tid + j * 512;
            int row = c >> 5, i = c & 31;
            long rr = ld_idx(revp, e0s + row);
            cp_async16(sYb + (uint32_t)SYW(row, i >> 3, i & 7) * 4,
                       Yprev + (size_t)rr * H + i * 4);
        }
        cp_commit();
    }

    // B (hi/lo) resident per CTA
    #pragma unroll
    for (int it = 0; it < 4; it++) {
        int i = tid + it * 512;
        int r = i >> 4, c = i & 15;
        *(uint4*)(sBh + r * SA_STRIDE + c * 8) = __ldg(Bh4 + i);
        *(uint4*)(sBl + r * SA_STRIDE + c * 8) = __ldg(Bl4 + i);
    }
    if (MODE == 2) {
        for (int i = tid; i < BF * H; i += 512) sWb[i] = g_WbT[i];
    }
    __syncthreads();

    int wm = (wid >> 2) * 32;
    int wn = (wid & 3) * 32;

    for (int t = 0; t < TILES_PER_CTA; t++) {
        long e0 = (tile0 + t) * ETILE;

        if (MODE == 1) {
            cp_wait<0>();
            __syncthreads();                       // staged Y visible to all
        }

        // ---- build A rows: thread: row tid>>2 (0..127), 32-col chunk tid&3
        {
            int row = tid >> 2, q = tid & 3;
            long e = e0 + row;
            uint2* dh = (uint2*)(sAh + row * SA_STRIDE + q * 32);
            uint2* dl = (uint2*)(sAl + row * SA_STRIDE + q * 32);
            float4 hv[8];
            if (MODE == 2) {
                int s = ld_idx(srcp, e);
                const float4* pp = (const float4*)(Pn + (size_t)s * H + q * 32);
                float bb[BF];
                const float* br = bond + e * BF;
                #pragma unroll
                for (int k = 0; k < BF; k++) bb[k] = __ldg(br + k);
                #pragma unroll
                for (int i = 0; i < 8; i++) {
                    float4 a = __ldg(pp + i);
                    #pragma unroll
                    for (int k = 0; k < BF; k++) {
                        float4 w = *(const float4*)(sWb + k * H + q * 32 + i * 4);
                        a.x += bb[k] * w.x; a.y += bb[k] * w.y;
                        a.z += bb[k] * w.z; a.w += bb[k] * w.w;
                    }
                    hv[i] = a;
                }
            } else {
                int s = ld_idx(srcp, e);
                const float4* ps = (const float4*)(Sprev + (size_t)s * H + q * 32);
                #pragma unroll
                for (int i = 0; i < 8; i++) {
                    float4 sv = __ldg(ps + i);
                    float4 yv = *(const float4*)(sY + SYW(row, q, i));
                    hv[i] = make_float4(sv.x - yv.x, sv.y - yv.y, sv.z - yv.z, sv.w - yv.w);
                }
            }
            #pragma unroll
            for (int i = 0; i < 8; i++) {
                float4 a = hv[i];
                a.x = fmaxf(a.x, 0.f); a.y = fmaxf(a.y, 0.f);
                a.z = fmaxf(a.z, 0.f); a.w = fmaxf(a.w, 0.f);
                __nv_bfloat16 h0,h1,h2,h3,l0,l1,l2,l3;
                bsplit(a.x,h0,l0); bsplit(a.y,h1,l1); bsplit(a.z,h2,l2); bsplit(a.w,h3,l3);
                dh[i] = make_uint2(bpack(h0,h1), bpack(h2,h3));
                dl[i] = make_uint2(bpack(l0,l1), bpack(l2,l3));
            }
        }
        __syncthreads();                           // A ready; stage consumed

        // ---- issue stage(t+1) prefetch; lands during mainloop/epilogue
        if (MODE == 1 && t + 1 < TILES_PER_CTA) {
            long e0n = (tile0 + t + 1) * ETILE;
            #pragma unroll
            for (int j = 0; j < 8; j++) {
                int c = tid + j * 512;
                int row = c >> 5, i = c & 31;
                long rr = ld_idx(revp, e0n + row);
                cp_async16(sYb + (uint32_t)SYW(row, i >> 3, i & 7) * 4,
                           Yprev + (size_t)rr * H + i * 4);
            }
            cp_commit();
        }

        // ---- fused-kstep mainloop: each fragment loaded once, 3 passes of mma
        float acc[2][4][4];
        #pragma unroll
        for (int mt = 0; mt < 2; mt++)
            #pragma unroll
            for (int nt = 0; nt < 4; nt++)
                #pragma unroll
                for (int i = 0; i < 4; i++) acc[mt][nt][i] = 0.f;

        {
            uint32_t aoff = ((uint32_t)(wm + (lane & 15)) * SA_STRIDE + (lane >> 4) * 8) * 2;
            uint32_t boff = ((uint32_t)(wn + (lane & 7)) * SA_STRIDE + ((lane >> 3) & 1) * 8) * 2;
            uint32_t aH = smem_u32(sAh) + aoff;
            uint32_t aL = smem_u32(sAl) + aoff;
            uint32_t bH = smem_u32(sBh) + boff;
            uint32_t bL = smem_u32(sBl) + boff;
            const uint32_t rstep = 16 * SA_STRIDE * 2;
            const uint32_t nstep = 8 * SA_STRIDE * 2;
            #pragma unroll
            for (int ks = 0; ks < 8; ks++) {
                uint32_t koff = (uint32_t)ks * 32;
                uint32_t a0h[4], a1h[4], a0l[4], a1l[4];
                ldsm_x4(a0h, aH + koff);
                ldsm_x4(a1h, aH + rstep + koff);
                ldsm_x4(a0l, aL + koff);
                ldsm_x4(a1l, aL + rstep + koff);
                uint32_t bh[4][2], bl[4][2];
                #pragma unroll
                for (int nt = 0; nt < 4; nt++) {
                    ldsm_x2(bh[nt], bH + (uint32_t)nt * nstep + koff);
                    ldsm_x2(bl[nt], bL + (uint32_t)nt * nstep + koff);
                }
                #pragma unroll
                for (int nt = 0; nt < 4; nt++) {
                    mma_bf16(acc[0][nt], a0h, bh[nt]);
                    mma_bf16(acc[1][nt], a1h, bh[nt]);
                    mma_bf16(acc[0][nt], a0l, bh[nt]);
                    mma_bf16(acc[1][nt], a1l, bh[nt]);
                    mma_bf16(acc[0][nt], a0h, bl[nt]);
                    mma_bf16(acc[1][nt], a1h, bl[nt]);
                }
            }
        }
        __syncthreads();

        // ---- D fragments -> smem fp32 (overlays sAh+sAl: 67584B <= 69632B)
        float* sD = (float*)sAh;
        {
            int g = lane >> 2, t2 = (lane & 3) * 2;
            #pragma unroll
            for (int mt = 0; mt < 2; mt++)
                #pragma unroll
                for (int nt = 0; nt < 4; nt++) {
                    int r0 = wm + mt * 16 + g, c0 = wn + nt * 8 + t2;
                    *(float2*)(sD + r0 * SD_STRIDE + c0)       = make_float2(acc[mt][nt][0], acc[mt][nt][1]);
                    *(float2*)(sD + (r0 + 8) * SD_STRIDE + c0) = make_float2(acc[mt][nt][2], acc[mt][nt][3]);
                }
        }
        __syncthreads();

        // ---- epilogue: thread: row tid&127, 32-col chunk tid>>7
        {
            int row = tid & 127, q = tid >> 7;
            long e = e0 + row;
            int d = ld_idx(dstp, e);
            const float4* sp = (const float4*)(sD + row * SD_STRIDE + q * 32);
            float* yrow = Yout + (size_t)e * H + q * 32;
            float* srow = Sout + (size_t)d * H + q * 32;
            #pragma unroll
            for (int i = 0; i < 8; i++) {
                float4 v = sp[i];
                *(float4*)(yrow + i * 4) = v;
                red4(srow + i * 4, v);
            }
        }
        __syncthreads();
    }
}

// ------- final combine: scatter relu(S2[src] - Y2[rev]) into S3[dst] --------
__global__ __launch_bounds__(256) void combine2(const float* __restrict__ S,
                                                const float* __restrict__ Yv,
                                                const void* __restrict__ src,
                                                const void* __restrict__ rev,
                                                float* __restrict__ S3,
                                                const void* __restrict__ dst) {
    long g = (long)blockIdx.x * 256 + threadIdx.x;
    long e = g >> 5;
    if (e >= NE) return;
    int q = (int)(g & 31) * 4;
    int s = ld_idx(src, e);
    long r = ld_idx(rev, e);
    int d = ld_idx(dst, e);
    float4 sv = *(const float4*)(S + (size_t)s * H + q);
    float4 yv = *(const float4*)(Yv + (size_t)r * H + q);
    float4 h;
    h.x = fmaxf(sv.x - yv.x, 0.f);
    h.y = fmaxf(sv.y - yv.y, 0.f);
    h.z = fmaxf(sv.z - yv.z, 0.f);
    h.w = fmaxf(sv.w - yv.w, 0.f);
    red4(S3 + (size_t)d * H + q, h);
}

// ---------------- launcher ----------------
extern "C" void kernel_launch(void* const* d_in, const int* in_sizes, int n_in,
                              void* d_out, int out_size) {
    const float* atom = (const float*)d_in[0];
    const float* bond = (const float*)d_in[1];
    const float* Wi   = (const float*)d_in[2];
    const float* Wh   = (const float*)d_in[3];
    const float* Wo   = (const float*)d_in[4];
    const void*  src  = d_in[5];
    const void*  dst  = d_in[6];
    const void*  rev  = d_in[7];
    float* out = (float*)d_out;

    __nv_bfloat16 *Bh, *Bl, *W1h, *W1l, *W2h, *W2l, *A1h, *A1l, *A2h, *A2l;
    float *y1, *y2, *P, *S1, *S2, *S3;
    cudaGetSymbolAddress((void**)&Bh, g_Bh);
    cudaGetSymbolAddress((void**)&Bl, g_Bl);
    cudaGetSymbolAddress((void**)&W1h, g_W1h);
    cudaGetSymbolAddress((void**)&W1l, g_W1l);
    cudaGetSymbolAddress((void**)&W2h, g_W2h);
    cudaGetSymbolAddress((void**)&W2l, g_W2l);
    cudaGetSymbolAddress((void**)&A1h, g_A1h);
    cudaGetSymbolAddress((void**)&A1l, g_A1l);
    cudaGetSymbolAddress((void**)&A2h, g_A2h);
    cudaGetSymbolAddress((void**)&A2l, g_A2l);
    cudaGetSymbolAddress((void**)&y1, g_y1);
    cudaGetSymbolAddress((void**)&y2, g_y2);
    cudaGetSymbolAddress((void**)&P,  g_P);
    cudaGetSymbolAddress((void**)&S1, g_S1);
    cudaGetSymbolAddress((void**)&S2, g_S2);
    cudaGetSymbolAddress((void**)&S3, g_S3);

    const int smemN  = 4 * NGMAT * 2;                       // 155648 B
    const int smemE1 = 4 * BMAT * 2 + 128 * SYROW * 4;      // 139264 + 75776 = 215040 B
    const int smemE2 = 4 * BMAT * 2 + BF * H * 4;           // 146432 B
    cudaFuncSetAttribute(ngemm<144, false>, cudaFuncAttributeMaxDynamicSharedMemorySize, smemN);
    cudaFuncSetAttribute(ngemm<288, true>,  cudaFuncAttributeMaxDynamicSharedMemorySize, smemN);
    cudaFuncSetAttribute(egemm<1>, cudaFuncAttributeMaxDynamicSharedMemorySize, smemE1);
    cudaFuncSetAttribute(egemm<2>, cudaFuncAttributeMaxDynamicSharedMemorySize, smemE2);

    // 1: prep (zeros + weights + atom panel + idx detect)
    prep_all<<<ZB + WB + CB + 1, 256>>>(Wi, Wh, Wo, atom, (const unsigned int*)src,
                                        (float4*)S1, (float4*)S2, (float4*)S3);
    // 2: P = atom @ Wa^T
    ngemm<144, false><<<NGRID, 512, smemN>>>(A1h, A1l, W1h, W1l, P);
    // 3: iter 1 (initial edge layer fused): A=relu(P[src]+bond@WbT); Y1, S1
    egemm<2><<<EGRID, 512, smemE2>>>(nullptr, nullptr, P, bond, src, nullptr,
                                     (const uint4*)Bh, (const uint4*)Bl, y1, S1, dst);
    // 4: iter 2: A=relu(S1[src]-Y1[rev]); Y2, S2   (ncu capture slot)
    egemm<1><<<EGRID, 512, smemE1>>>(S1, y1, nullptr, nullptr, src, rev,
                                     (const uint4*)Bh, (const uint4*)Bl, y2, S2, dst);
    // 5: scatter relu(S2[src]-Y2[rev]) into S3
    combine2<<<NE * 32 / 256, 256>>>(S2, y2, src, rev, S3, dst);
    // 6: [atom|S3] panel
    cvt2<<<(int)(((long)NROWS_PAD * 288 + 511) / 512), 512>>>(atom, S3);
    // 7: out = relu([atom|S3] @ Wo^T)
    ngemm<288, true><<<NGRID, 512, smemN>>>(A2h, A2l, W2h, W2l, out);
}

// round 9
// speedup vs baseline: 1.4297x; 1.3700x over previous
#include <cuda_runtime.h>
#include <cuda_bf16.h>
#include <cstdint>

#define NN 50000
#define NE 800000
#define AF 133
#define BF 14
#define H  128
#define SA_STRIDE 136
#define SD_STRIDE 132
#define BMAT (128 * SA_STRIDE)          // 34816 B per 128x128 bf16 smem matrix
#define ETILE 128
#define TILES_PER_CTA 5
#define EGRID (NE / ETILE / TILES_PER_CTA)   // 1250

#define NGS  152
#define NGMAT (128 * NGS)
#define NROWS_PAD 50048
#define NGRID 391

// ---------------- scratch ----------------
__device__ __nv_bfloat16 g_hh[(size_t)NE * H];
__device__ __nv_bfloat16 g_hl[(size_t)NE * H];
__device__ float g_y1[(size_t)NE * H];
__device__ float g_y2[(size_t)NE * H];
__device__ float g_P [(size_t)NN * H];
__device__ float g_S1[(size_t)NN * H];
__device__ float g_S2[(size_t)NN * H];
__device__ float g_S3[(size_t)NN * H];
__device__ float g_WbT[BF * H];
__device__ __nv_bfloat16 g_Bh[H * H];
__device__ __nv_bfloat16 g_Bl[H * H];
__device__ __nv_bfloat16 g_W1h[128 * 144];
__device__ __nv_bfloat16 g_W1l[128 * 144];
__device__ __nv_bfloat16 g_W2h[128 * 288];
__device__ __nv_bfloat16 g_W2l[128 * 288];
__device__ __nv_bfloat16 g_A1h[(size_t)NROWS_PAD * 144];
__device__ __nv_bfloat16 g_A1l[(size_t)NROWS_PAD * 144];
__device__ __nv_bfloat16 g_A2h[(size_t)NROWS_PAD * 288];
__device__ __nv_bfloat16 g_A2l[(size_t)NROWS_PAD * 288];
__device__ int   g_idx64;

// ---------------- helpers ----------------
__device__ __forceinline__ int ld_idx(const void* p, long i) {
    if (g_idx64) return (int)__ldg((const long long*)p + i);
    return __ldg((const int*)p + i);
}
__device__ __forceinline__ void red4(float* p, float4 v) {
    asm volatile("red.global.add.v4.f32 [%0], {%1,%2,%3,%4};"
                 :: "l"(p), "f"(v.x), "f"(v.y), "f"(v.z), "f"(v.w) : "memory");
}
__device__ __forceinline__ uint32_t smem_u32(const void* p) {
    uint32_t a;
    asm("{ .reg .u64 t; cvta.to.shared.u64 t, %1; cvt.u32.u64 %0, t; }" : "=r"(a) : "l"(p));
    return a;
}
__device__ __forceinline__ void cp_async16(uint32_t sdst, const void* gsrc) {
    asm volatile("cp.async.cg.shared.global [%0], [%1], 16;" :: "r"(sdst), "l"(gsrc) : "memory");
}
__device__ __forceinline__ void cp_commit() {
    asm volatile("cp.async.commit_group;" ::: "memory");
}
template<int N> __device__ __forceinline__ void cp_wait() {
    asm volatile("cp.async.wait_group %0;" :: "n"(N) : "memory");
}
__device__ __forceinline__ void bsplit(float v, __nv_bfloat16& h, __nv_bfloat16& l) {
    h = __float2bfloat16(v);
    l = __float2bfloat16(v - __bfloat162float(h));
}
__device__ __forceinline__ uint32_t bpack(__nv_bfloat16 a, __nv_bfloat16 b) {
    return ((uint32_t)__bfloat16_as_ushort(b) << 16) | (uint32_t)__bfloat16_as_ushort(a);
}
__device__ __forceinline__ void ldsm_x4(uint32_t (&r)[4], uint32_t addr) {
    asm volatile("ldmatrix.sync.aligned.m8n8.x4.shared.b16 {%0,%1,%2,%3}, [%4];"
                 : "=r"(r[0]), "=r"(r[1]), "=r"(r[2]), "=r"(r[3]) : "r"(addr));
}
__device__ __forceinline__ void ldsm_x2(uint32_t (&r)[2], uint32_t addr) {
    asm volatile("ldmatrix.sync.aligned.m8n8.x2.shared.b16 {%0,%1}, [%2];"
                 : "=r"(r[0]), "=r"(r[1]) : "r"(addr));
}
__device__ __forceinline__ void mma_bf16(float (&d)[4], const uint32_t (&a)[4], const uint32_t (&b)[2]) {
    asm volatile("mma.sync.aligned.m16n8k16.row.col.f32.bf16.bf16.f32 "
                 "{%0,%1,%2,%3}, {%4,%5,%6,%7}, {%8,%9}, {%0,%1,%2,%3};"
                 : "+f"(d[0]), "+f"(d[1]), "+f"(d[2]), "+f"(d[3])
                 : "r"(a[0]), "r"(a[1]), "r"(a[2]), "r"(a[3]), "r"(b[0]), "r"(b[1]));
}

// ======= prep_all: zero S bufs | weight prep | atom panel | idx detect ======
#define ZB 18750
#define WB 144
#define CB 28152
__global__ __launch_bounds__(256) void prep_all(
    const float* __restrict__ Wi, const float* __restrict__ Wh,
    const float* __restrict__ Wo, const float* __restrict__ atom,
    const unsigned int* __restrict__ srcw,
    float4* __restrict__ S1, float4* __restrict__ S2, float4* __restrict__ S3)
{
    int b = blockIdx.x;
    if (b < ZB) {
        const long n = (long)NN * H / 4;
        long i = (long)b * 256 + threadIdx.x;
        float4 z = make_float4(0.f, 0.f, 0.f, 0.f);
        if (i < n) S1[i] = z;
        else if (i < 2 * n) S2[i - n] = z;
        else S3[i - 2 * n] = z;
        return;
    }
    b -= ZB;
    if (b < WB) {
        int i = b * 256 + threadIdx.x;
        if (i >= 128 * 288) return;
        if (i < BF * H) {
            int j = i & 127, k = i >> 7;
            g_WbT[i] = Wi[j * (AF + BF) + AF + k];
        }
        if (i < H * H) {
            __nv_bfloat16 hi, lo; bsplit(Wh[i], hi, lo);
            g_Bh[i] = hi; g_Bl[i] = lo;
        }
        if (i < 128 * 144) {
            int n = i / 144, k = i % 144;
            float v = (k < AF) ? Wi[n * (AF + BF) + k] : 0.f;
            __nv_bfloat16 hi, lo; bsplit(v, hi, lo);
            g_W1h[i] = hi; g_W1l[i] = lo;
        }
        {
            int n = i / 288, k = i % 288;
            float v = (k < AF + H) ? Wo[n * (AF + H) + k] : 0.f;
            __nv_bfloat16 hi, lo; bsplit(v, hi, lo);
            g_W2h[i] = hi; g_W2l[i] = lo;
        }
        return;
    }
    b -= WB;
    if (b < CB) {
        long i = (long)b * 256 + threadIdx.x;
        int r = (int)(i / 144), c = (int)(i % 144);
        float v = (r < NN && c < AF) ? __ldg(atom + (size_t)r * AF + c) : 0.f;
        __nv_bfloat16 hi, lo; bsplit(v, hi, lo);
        g_A1h[i] = hi; g_A1l[i] = lo;
        return;
    }
    __shared__ unsigned int s;
    if (threadIdx.x == 0) s = 0;
    __syncthreads();
    unsigned int v = srcw[threadIdx.x * 2 + 1] | srcw[2048 + threadIdx.x * 2 + 1];
    atomicOr(&s, v);
    __syncthreads();
    if (threadIdx.x == 0) g_idx64 = (s == 0u) ? 1 : 0;
}

// ---------------- cvt2: [atom|S3] panel ----------------
__global__ void cvt2(const float* __restrict__ atom, const float* __restrict__ S3) {
    long i = (long)blockIdx.x * blockDim.x + threadIdx.x;
    if (i >= (long)NROWS_PAD * 288) return;
    int r = (int)(i / 288), c = (int)(i % 288);
    float v = 0.f;
    if (r < NN) {
        if (c < AF) v = __ldg(atom + (size_t)r * AF + c);
        else if (c < AF + H) v = __ldg(S3 + (size_t)r * H + (c - AF));
    }
    __nv_bfloat16 hi, lo; bsplit(v, hi, lo);
    g_A2h[i] = hi; g_A2l[i] = lo;
}

// ---------------- node GEMM via mma.sync (proven R6) --------------------------
template<int KPAD, bool RELU>
__global__ __launch_bounds__(512, 1) void ngemm(
    const __nv_bfloat16* __restrict__ Ahg, const __nv_bfloat16* __restrict__ Alg,
    const __nv_bfloat16* __restrict__ Whg, const __nv_bfloat16* __restrict__ Wlg,
    float* __restrict__ out)
{
    extern __shared__ __align__(16) char dyn[];
    __nv_bfloat16* sBh = (__nv_bfloat16*)dyn;
    __nv_bfloat16* sBl = sBh + NGMAT;
    __nv_bfloat16* sAh = sBl + NGMAT;
    __nv_bfloat16* sAl = sAh + NGMAT;

    int tid = threadIdx.x, lane = tid & 31, wid = tid >> 5;
    int m0 = blockIdx.x * 128;
    int wm = (wid >> 2) * 32, wn = (wid & 3) * 32;

    float acc[2][4][4];
    #pragma unroll
    for (int mt = 0; mt < 2; mt++)
        #pragma unroll
        for (int nt = 0; nt < 4; nt++)
            #pragma unroll
            for (int i = 0; i < 4; i++) acc[mt][nt][i] = 0.f;

    const int NCH = KPAD / 144;
    #pragma unroll
    for (int ch = 0; ch < NCH; ch++) {
        if (ch) __syncthreads();
        for (int i = tid; i < 128 * 18; i += 512) {
            int r = i / 18, c = i % 18;
            int go = r * KPAD + ch * 144 + c * 8;
            *(uint4*)(sBh + r * NGS + c * 8) = *(const uint4*)(Whg + go);
            *(uint4*)(sBl + r * NGS + c * 8) = *(const uint4*)(Wlg + go);
        }
        for (int i = tid; i < 128 * 18; i += 512) {
            int r = i / 18, c = i % 18;
            size_t go = (size_t)(m0 + r) * KPAD + ch * 144 + c * 8;
            *(uint4*)(sAh + r * NGS + c * 8) = *(const uint4*)(Ahg + go);
            *(uint4*)(sAl + r * NGS + c * 8) = *(const uint4*)(Alg + go);
        }
        __syncthreads();

        #pragma unroll
        for (int pass = 0; pass < 3; pass++) {
            uint32_t abase = smem_u32(pass == 1 ? sAl : sAh);
            uint32_t bbase = smem_u32(pass == 2 ? sBl : sBh);
            uint32_t aAddr0 = abase + ((uint32_t)(wm + (lane & 15)) * NGS + (lane >> 4) * 8) * 2;
            uint32_t aAddr1 = aAddr0 + 16 * NGS * 2;
            uint32_t bAddr  = bbase + ((uint32_t)(wn + (lane & 7)) * NGS + ((lane >> 3) & 1) * 8) * 2;
            #pragma unroll
            for (int ks = 0; ks < 9; ks++) {
                uint32_t koff = (uint32_t)ks * 32;
                uint32_t a0[4], a1[4];
                ldsm_x4(a0, aAddr0 + koff);
                ldsm_x4(a1, aAddr1 + koff);
                uint32_t b[4][2];
                #pragma unroll
                for (int nt = 0; nt < 4; nt++)
                    ldsm_x2(b[nt], bAddr + (uint32_t)nt * 8 * NGS * 2 + koff);
                #pragma unroll
                for (int nt = 0; nt < 4; nt++) {
                    mma_bf16(acc[0][nt], a0, b[nt]);
                    mma_bf16(acc[1][nt], a1, b[nt]);
                }
            }
        }
    }
    __syncthreads();

    float* sD = (float*)sAh;
    {
        int g = lane >> 2, t2 = (lane & 3) * 2;
        #pragma unroll
        for (int mt = 0; mt < 2; mt++)
            #pragma unroll
            for (int nt = 0; nt < 4; nt++) {
                int r0 = wm + mt * 16 + g, c0 = wn + nt * 8 + t2;
                float2 v0 = make_float2(acc[mt][nt][0], acc[mt][nt][1]);
                float2 v1 = make_float2(acc[mt][nt][2], acc[mt][nt][3]);
                if (RELU) {
                    v0.x = fmaxf(v0.x, 0.f); v0.y = fmaxf(v0.y, 0.f);
                    v1.x = fmaxf(v1.x, 0.f); v1.y = fmaxf(v1.y, 0.f);
                }
                *(float2*)(sD + r0 * SD_STRIDE + c0)       = v0;
                *(float2*)(sD + (r0 + 8) * SD_STRIDE + c0) = v1;
            }
    }
    __syncthreads();
    {
        int row = tid & 127, q = tid >> 7;
        if (m0 + row < NN) {
            const float4* sp = (const float4*)(sD + row * SD_STRIDE + q * 32);
            float* orow = out + (size_t)(m0 + row) * H + q * 32;
            #pragma unroll
            for (int i = 0; i < 8; i++) *(float4*)(orow + i * 4) = sp[i];
        }
    }
}

// ---- initial edge layer: h0 = relu(P[src] + bond @ WbT) (bf16 hi/lo) -------
__global__ __launch_bounds__(256) void init_edges(const float* __restrict__ bond,
                                                  const void* __restrict__ src) {
    __shared__ float sWb[BF * H];
    for (int i = threadIdx.x; i < BF * H; i += 256) sWb[i] = g_WbT[i];
    __syncthreads();
    int warp = threadIdx.x >> 5, lane = threadIdx.x & 31;
    for (long e0 = (long)blockIdx.x * 8; e0 < NE; e0 += (long)gridDim.x * 8) {
        long e = e0 + warp;
        int s = ld_idx(src, e);
        int q = lane * 4;
        float4 acc = *(const float4*)(g_P + (size_t)s * H + q);
        const float* br = bond + e * BF;
        #pragma unroll
        for (int k = 0; k < BF; k++) {
            float b = __ldg(br + k);
            float4 w = *(const float4*)(sWb + k * H + q);
            acc.x += b * w.x; acc.y += b * w.y; acc.z += b * w.z; acc.w += b * w.w;
        }
        acc.x = fmaxf(acc.x, 0.f); acc.y = fmaxf(acc.y, 0.f);
        acc.z = fmaxf(acc.z, 0.f); acc.w = fmaxf(acc.w, 0.f);
        __nv_bfloat16 h0,h1,h2,h3,l0,l1,l2,l3;
        bsplit(acc.x,h0,l0); bsplit(acc.y,h1,l1); bsplit(acc.z,h2,l2); bsplit(acc.w,h3,l3);
        size_t off = (size_t)e * H + q;
        *(uint2*)(g_hh + off) = make_uint2(bpack(h0,h1), bpack(h2,h3));
        *(uint2*)(g_hl + off) = make_uint2(bpack(l0,l1), bpack(l2,l3));
    }
}

// ---------------- edge GEMM: pure streaming MODE 0 ---------------------------
// A (hi/lo) from g_hh/g_hl via cp.async double-buffer (prefetch t+1 first,
// then wait_group 1 — R5-proven order). Fused-kstep mainloop (R8-proven).
// Epilogue: Y write + red.add.v4 scatter into Sout[dst].
__global__ __launch_bounds__(512, 1) void egemm0(
    const __nv_bfloat16* __restrict__ Ah, const __nv_bfloat16* __restrict__ Al,
    const uint4* __restrict__ Bh4,  const uint4* __restrict__ Bl4,
    float* __restrict__ Yout, float* __restrict__ Sout,
    const void* __restrict__ dstp)
{
    extern __shared__ __align__(16) char dyn[];
    __nv_bfloat16* sBh = (__nv_bfloat16*)dyn;
    __nv_bfloat16* sBl = sBh + BMAT;
    __nv_bfloat16* sSt0 = sBl + BMAT;          // stage: Ah|Al (2*BMAT)
    __nv_bfloat16* sSt1 = sSt0 + 2 * BMAT;

    int tid = threadIdx.x, lane = tid & 31, wid = tid >> 5;
    long tile0 = (long)blockIdx.x * TILES_PER_CTA;

    // prefetch tile 0 into stage 0 (before B so the DRAM fetch starts early)
    {
        uint32_t st = smem_u32(sSt0);
        long e0 = tile0 * ETILE;
        #pragma unroll
        for (int it = 0; it < 4; it++) {
            int i = tid + it * 512;
            int r = i >> 4, c = i & 15;
            uint32_t doff = (uint32_t)(r * SA_STRIDE + c * 8) * 2;
            cp_async16(st + doff, Ah + (size_t)(e0 + r) * H + c * 8);
            cp_async16(st + (uint32_t)BMAT * 2 + doff, Al + (size_t)(e0 + r) * H + c * 8);
        }
        cp_commit();
    }

    // B (hi/lo) resident
    #pragma unroll
    for (int it = 0; it < 4; it++) {
        int i = tid + it * 512;
        int r = i >> 4, c = i & 15;
        *(uint4*)(sBh + r * SA_STRIDE + c * 8) = __ldg(Bh4 + i);
        *(uint4*)(sBl + r * SA_STRIDE + c * 8) = __ldg(Bl4 + i);
    }

    int wm = (wid >> 2) * 32;
    int wn = (wid & 3) * 32;

    for (int t = 0; t < TILES_PER_CTA; t++) {
        long e0 = (tile0 + t) * ETILE;
        __nv_bfloat16* sA = (t & 1) ? sSt1 : sSt0;

        // issue prefetch(t+1) into other stage FIRST, then drain tile t
        if (t + 1 < TILES_PER_CTA) {
            __nv_bfloat16* nx = (t & 1) ? sSt0 : sSt1;
            uint32_t st = smem_u32(nx);
            long en = (tile0 + t + 1) * ETILE;
            #pragma unroll
            for (int it = 0; it < 4; it++) {
                int i = tid + it * 512;
                int r = i >> 4, c = i & 15;
                uint32_t doff = (uint32_t)(r * SA_STRIDE + c * 8) * 2;
                cp_async16(st + doff, Ah + (size_t)(en + r) * H + c * 8);
                cp_async16(st + (uint32_t)BMAT * 2 + doff, Al + (size_t)(en + r) * H + c * 8);
            }
            cp_commit();
            cp_wait<1>();
        } else {
            cp_wait<0>();
        }
        __syncthreads();

        // ---- fused-kstep mainloop
        float acc[2][4][4];
        #pragma unroll
        for (int mt = 0; mt < 2; mt++)
            #pragma unroll
            for (int nt = 0; nt < 4; nt++)
                #pragma unroll
                for (int i = 0; i < 4; i++) acc[mt][nt][i] = 0.f;

        {
            uint32_t aoff = ((uint32_t)(wm + (lane & 15)) * SA_STRIDE + (lane >> 4) * 8) * 2;
            uint32_t boff = ((uint32_t)(wn + (lane & 7)) * SA_STRIDE + ((lane >> 3) & 1) * 8) * 2;
            uint32_t aH = smem_u32(sA) + aoff;
            uint32_t aL = aH + (uint32_t)BMAT * 2;
            uint32_t bH = smem_u32(sBh) + boff;
            uint32_t bL = smem_u32(sBl) + boff;
            const uint32_t rstep = 16 * SA_STRIDE * 2;
            const uint32_t nstep = 8 * SA_STRIDE * 2;
            #pragma unroll
            for (int ks = 0; ks < 8; ks++) {
                uint32_t koff = (uint32_t)ks * 32;
                uint32_t a0h[4], a1h[4], a0l[4], a1l[4];
                ldsm_x4(a0h, aH + koff);
                ldsm_x4(a1h, aH + rstep + koff);
                ldsm_x4(a0l, aL + koff);
                ldsm_x4(a1l, aL + rstep + koff);
                uint32_t bh[4][2], bl[4][2];
                #pragma unroll
                for (int nt = 0; nt < 4; nt++) {
                    ldsm_x2(bh[nt], bH + (uint32_t)nt * nstep + koff);
                    ldsm_x2(bl[nt], bL + (uint32_t)nt * nstep + koff);
                }
                #pragma unroll
                for (int nt = 0; nt < 4; nt++) {
                    mma_bf16(acc[0][nt], a0h, bh[nt]);
                    mma_bf16(acc[1][nt], a1h, bh[nt]);
                    mma_bf16(acc[0][nt], a0l, bh[nt]);
                    mma_bf16(acc[1][nt], a1l, bh[nt]);
                    mma_bf16(acc[0][nt], a0h, bl[nt]);
                    mma_bf16(acc[1][nt], a1h, bl[nt]);
                }
            }
        }
        __syncthreads();

        // ---- D -> smem fp32 (overlays current stage; 67584B <= 69632B)
        float* sD = (float*)sA;
        {
            int g = lane >> 2, t2 = (lane & 3) * 2;
            #pragma unroll
            for (int mt = 0; mt < 2; mt++)
                #pragma unroll
                for (int nt = 0; nt < 4; nt++) {
                    int r0 = wm + mt * 16 + g, c0 = wn + nt * 8 + t2;
                    *(float2*)(sD + r0 * SD_STRIDE + c0)       = make_float2(acc[mt][nt][0], acc[mt][nt][1]);
                    *(float2*)(sD + (r0 + 8) * SD_STRIDE + c0) = make_float2(acc[mt][nt][2], acc[mt][nt][3]);
                }
        }
        __syncthreads();

        // ---- epilogue
        {
            int row = tid & 127, q = tid >> 7;
            long e = e0 + row;
            int d = ld_idx(dstp, e);
            const float4* sp = (const float4*)(sD + row * SD_STRIDE + q * 32);
            float* yrow = Yout + (size_t)e * H + q * 32;
            float* srow = Sout + (size_t)d * H + q * 32;
            #pragma unroll
            for (int i = 0; i < 8; i++) {
                float4 v = sp[i];
                *(float4*)(yrow + i * 4) = v;
                red4(srow + i * 4, v);
            }
        }
        __syncthreads();
    }
}

// ------- combine1: h = relu(S[src] - Y[rev]) -> g_hh/g_hl (streaming) --------
__global__ __launch_bounds__(256) void combine1(const float* __restrict__ S,
                                                const float* __restrict__ Yv,
                                                const void* __restrict__ src,
                                                const void* __restrict__ rev) {
    long g = (long)blockIdx.x * 256 + threadIdx.x;
    long e = g >> 5;
    if (e >= NE) return;
    int q = (int)(g & 31) * 4;
    int s = ld_idx(src, e);
    long r = ld_idx(rev, e);
    float4 sv = *(const float4*)(S + (size_t)s * H + q);
    float4 yv = *(const float4*)(Yv + (size_t)r * H + q);
    float4 h;
    h.x = fmaxf(sv.x - yv.x, 0.f);
    h.y = fmaxf(sv.y - yv.y, 0.f);
    h.z = fmaxf(sv.z - yv.z, 0.f);
    h.w = fmaxf(sv.w - yv.w, 0.f);
    __nv_bfloat16 h0,h1,h2,h3,l0,l1,l2,l3;
    bsplit(h.x,h0,l0); bsplit(h.y,h1,l1); bsplit(h.z,h2,l2); bsplit(h.w,h3,l3);
    size_t off = (size_t)e * H + q;
    *(uint2*)(g_hh + off) = make_uint2(bpack(h0,h1), bpack(h2,h3));
    *(uint2*)(g_hl + off) = make_uint2(bpack(l0,l1), bpack(l2,l3));
}

// ------- combine2: scatter relu(S[src] - Y[rev]) into S3[dst] ----------------
__global__ __launch_bounds__(256) void combine2(const float* __restrict__ S,
                                                const float* __restrict__ Yv,
                                                const void* __restrict__ src,
                                                const void* __restrict__ rev,
                                                float* __restrict__ S3,
                                                const void* __restrict__ dst) {
    long g = (long)blockIdx.x * 256 + threadIdx.x;
    long e = g >> 5;
    if (e >= NE) return;
    int q = (int)(g & 31) * 4;
    int s = ld_idx(src, e);
    long r = ld_idx(rev, e);
    int d = ld_idx(dst, e);
    float4 sv = *(const float4*)(S + (size_t)s * H + q);
    float4 yv = *(const float4*)(Yv + (size_t)r * H + q);
    float4 h;
    h.x = fmaxf(sv.x - yv.x, 0.f);
    h.y = fmaxf(sv.y - yv.y, 0.f);
    h.z = fmaxf(sv.z - yv.z, 0.f);
    h.w = fmaxf(sv.w - yv.w, 0.f);
    red4(S3 + (size_t)d * H + q, h);
}

// ---------------- launcher ----------------
extern "C" void kernel_launch(void* const* d_in, const int* in_sizes, int n_in,
                              void* d_out, int out_size) {
    const float* atom = (const float*)d_in[0];
    const float* bond = (const float*)d_in[1];
    const float* Wi   = (const float*)d_in[2];
    const float* Wh   = (const float*)d_in[3];
    const float* Wo   = (const float*)d_in[4];
    const void*  src  = d_in[5];
    const void*  dst  = d_in[6];
    const void*  rev  = d_in[7];
    float* out = (float*)d_out;

    __nv_bfloat16 *hh, *hl, *Bh, *Bl, *W1h, *W1l, *W2h, *W2l, *A1h, *A1l, *A2h, *A2l;
    float *y1, *y2, *P, *S1, *S2, *S3;
    cudaGetSymbolAddress((void**)&hh, g_hh);
    cudaGetSymbolAddress((void**)&hl, g_hl);
    cudaGetSymbolAddress((void**)&Bh, g_Bh);
    cudaGetSymbolAddress((void**)&Bl, g_Bl);
    cudaGetSymbolAddress((void**)&W1h, g_W1h);
    cudaGetSymbolAddress((void**)&W1l, g_W1l);
    cudaGetSymbolAddress((void**)&W2h, g_W2h);
    cudaGetSymbolAddress((void**)&W2l, g_W2l);
    cudaGetSymbolAddress((void**)&A1h, g_A1h);
    cudaGetSymbolAddress((void**)&A1l, g_A1l);
    cudaGetSymbolAddress((void**)&A2h, g_A2h);
    cudaGetSymbolAddress((void**)&A2l, g_A2l);
    cudaGetSymbolAddress((void**)&y1, g_y1);
    cudaGetSymbolAddress((void**)&y2, g_y2);
    cudaGetSymbolAddress((void**)&P,  g_P);
    cudaGetSymbolAddress((void**)&S1, g_S1);
    cudaGetSymbolAddress((void**)&S2, g_S2);
    cudaGetSymbolAddress((void**)&S3, g_S3);

    const int smemN  = 4 * NGMAT * 2;    // 155648 B
    const int smemE0 = 6 * BMAT * 2;     // B(2) + 2 stages(2 each) = 208896 B
    cudaFuncSetAttribute(ngemm<144, false>, cudaFuncAttributeMaxDynamicSharedMemorySize, smemN);
    cudaFuncSetAttribute(ngemm<288, true>,  cudaFuncAttributeMaxDynamicSharedMemorySize, smemN);
    cudaFuncSetAttribute(egemm0, cudaFuncAttributeMaxDynamicSharedMemorySize, smemE0);

    // 1: prep (zeros + weights + atom panel + idx detect)
    prep_all<<<ZB + WB + CB + 1, 256>>>(Wi, Wh, Wo, atom, (const unsigned int*)src,
                                        (float4*)S1, (float4*)S2, (float4*)S3);
    // 2: P = atom @ Wa^T
    ngemm<144, false><<<NGRID, 512, smemN>>>(A1h, A1l, W1h, W1l, P);
    // 3: h0 = relu(P[src] + bond @ WbT)  (streaming)
    init_edges<<<2048, 256>>>(bond, src);
    // 4: iter 1: Y1 = h0 @ Wh^T, scatter S1   (ncu capture slot)
    egemm0<<<EGRID, 512, smemE0>>>(hh, hl, (const uint4*)Bh, (const uint4*)Bl, y1, S1, dst);
    // 5: h1 = relu(S1[src] - Y1[rev])  (streaming)
    combine1<<<NE * 32 / 256, 256>>>(S1, y1, src, rev);
    // 6: iter 2: Y2 = h1 @ Wh^T, scatter S2
    egemm0<<<EGRID, 512, smemE0>>>(hh, hl, (const uint4*)Bh, (const uint4*)Bl, y2, S2, dst);
    // 7: scatter relu(S2[src] - Y2[rev]) into S3
    combine2<<<NE * 32 / 256, 256>>>(S2, y2, src, rev, S3, dst);
    // 8: [atom|S3] panel
    cvt2<<<(int)(((long)NROWS_PAD * 288 + 511) / 512), 512>>>(atom, S3);
    // 9: out = relu([atom|S3] @ Wo^T)
    ngemm<288, true><<<NGRID, 512, smemN>>>(A2h, A2l, W2h, W2l, out);
}

// round 10
// speedup vs baseline: 1.5096x; 1.0559x over previous
#include <cuda_runtime.h>
#include <cuda_bf16.h>
#include <cuda_fp16.h>
#include <cstdint>

#define NN 50000
#define NE 800000
#define AF 133
#define BF 14
#define H  128
#define SA_STRIDE 136
#define SD_STRIDE 132
#define BMAT (128 * SA_STRIDE)          // 34816 B per 128x128 bf16 smem matrix
#define ETILE 128
#define TILES_PER_CTA 5
#define EGRID (NE / ETILE / TILES_PER_CTA)   // 1250

#define NGS  152
#define NGMAT (128 * NGS)
#define NROWS_PAD 50048
#define NGRID 391

// ---------------- scratch ----------------
__device__ __nv_bfloat16 g_hh[(size_t)NE * H];
__device__ __nv_bfloat16 g_hl[(size_t)NE * H];
__device__ __half g_y1[(size_t)NE * H];            // Y in fp16 (halved traffic)
__device__ __half g_y2[(size_t)NE * H];
__device__ float g_P [(size_t)NN * H];
__device__ float g_S1[(size_t)NN * H];
__device__ float g_S2[(size_t)NN * H];
__device__ float g_S3[(size_t)NN * H];
__device__ float g_WbT[BF * H];
__device__ __nv_bfloat16 g_Bh[H * H];
__device__ __nv_bfloat16 g_Bl[H * H];
__device__ __nv_bfloat16 g_W1h[128 * 144];
__device__ __nv_bfloat16 g_W1l[128 * 144];
__device__ __nv_bfloat16 g_W2h[128 * 288];
__device__ __nv_bfloat16 g_W2l[128 * 288];
__device__ __nv_bfloat16 g_A1h[(size_t)NROWS_PAD * 144];
__device__ __nv_bfloat16 g_A1l[(size_t)NROWS_PAD * 144];
__device__ __nv_bfloat16 g_A2h[(size_t)NROWS_PAD * 288];
__device__ __nv_bfloat16 g_A2l[(size_t)NROWS_PAD * 288];
__device__ int   g_idx64;

// ---------------- helpers ----------------
__device__ __forceinline__ int ld_idx(const void* p, long i) {
    if (g_idx64) return (int)__ldg((const long long*)p + i);
    return __ldg((const int*)p + i);
}
__device__ __forceinline__ void red4(float* p, float4 v) {
    asm volatile("red.global.add.v4.f32 [%0], {%1,%2,%3,%4};"
                 :: "l"(p), "f"(v.x), "f"(v.y), "f"(v.z), "f"(v.w) : "memory");
}
__device__ __forceinline__ uint32_t smem_u32(const void* p) {
    uint32_t a;
    asm("{ .reg .u64 t; cvta.to.shared.u64 t, %1; cvt.u32.u64 %0, t; }" : "=r"(a) : "l"(p));
    return a;
}
__device__ __forceinline__ void cp_async16(uint32_t sdst, const void* gsrc) {
    asm volatile("cp.async.cg.shared.global [%0], [%1], 16;" :: "r"(sdst), "l"(gsrc) : "memory");
}
__device__ __forceinline__ void cp_commit() {
    asm volatile("cp.async.commit_group;" ::: "memory");
}
template<int N> __device__ __forceinline__ void cp_wait() {
    asm volatile("cp.async.wait_group %0;" :: "n"(N) : "memory");
}
__device__ __forceinline__ void bsplit(float v, __nv_bfloat16& h, __nv_bfloat16& l) {
    h = __float2bfloat16(v);
    l = __float2bfloat16(v - __bfloat162float(h));
}
__device__ __forceinline__ uint32_t bpack(__nv_bfloat16 a, __nv_bfloat16 b) {
    return ((uint32_t)__bfloat16_as_ushort(b) << 16) | (uint32_t)__bfloat16_as_ushort(a);
}
__device__ __forceinline__ void ldsm_x4(uint32_t (&r)[4], uint32_t addr) {
    asm volatile("ldmatrix.sync.aligned.m8n8.x4.shared.b16 {%0,%1,%2,%3}, [%4];"
                 : "=r"(r[0]), "=r"(r[1]), "=r"(r[2]), "=r"(r[3]) : "r"(addr));
}
__device__ __forceinline__ void ldsm_x2(uint32_t (&r)[2], uint32_t addr) {
    asm volatile("ldmatrix.sync.aligned.m8n8.x2.shared.b16 {%0,%1}, [%2];"
                 : "=r"(r[0]), "=r"(r[1]) : "r"(addr));
}
__device__ __forceinline__ void mma_bf16(float (&d)[4], const uint32_t (&a)[4], const uint32_t (&b)[2]) {
    asm volatile("mma.sync.aligned.m16n8k16.row.col.f32.bf16.bf16.f32 "
                 "{%0,%1,%2,%3}, {%4,%5,%6,%7}, {%8,%9}, {%0,%1,%2,%3};"
                 : "+f"(d[0]), "+f"(d[1]), "+f"(d[2]), "+f"(d[3])
                 : "r"(a[0]), "r"(a[1]), "r"(a[2]), "r"(a[3]), "r"(b[0]), "r"(b[1]));
}
// load 4 consecutive fp16 Y values -> float4
__device__ __forceinline__ float4 ld_y4(const __half* p) {
    uint2 raw = __ldg((const uint2*)p);
    __half2 h01 = *(__half2*)&raw.x;
    __half2 h23 = *(__half2*)&raw.y;
    float2 f01 = __half22float2(h01);
    float2 f23 = __half22float2(h23);
    return make_float4(f01.x, f01.y, f23.x, f23.y);
}

// ======= prep_all: zero S bufs | weight prep | atom panel | idx detect ======
#define ZB 18750
#define WB 144
#define CB 28152
__global__ __launch_bounds__(256) void prep_all(
    const float* __restrict__ Wi, const float* __restrict__ Wh,
    const float* __restrict__ Wo, const float* __restrict__ atom,
    const unsigned int* __restrict__ srcw,
    float4* __restrict__ S1, float4* __restrict__ S2, float4* __restrict__ S3)
{
    int b = blockIdx.x;
    if (b < ZB) {
        const long n = (long)NN * H / 4;
        long i = (long)b * 256 + threadIdx.x;
        float4 z = make_float4(0.f, 0.f, 0.f, 0.f);
        if (i < n) S1[i] = z;
        else if (i < 2 * n) S2[i - n] = z;
        else S3[i - 2 * n] = z;
        return;
    }
    b -= ZB;
    if (b < WB) {
        int i = b * 256 + threadIdx.x;
        if (i >= 128 * 288) return;
        if (i < BF * H) {
            int j = i & 127, k = i >> 7;
            g_WbT[i] = Wi[j * (AF + BF) + AF + k];
        }
        if (i < H * H) {
            __nv_bfloat16 hi, lo; bsplit(Wh[i], hi, lo);
            g_Bh[i] = hi; g_Bl[i] = lo;
        }
        if (i < 128 * 144) {
            int n = i / 144, k = i % 144;
            float v = (k < AF) ? Wi[n * (AF + BF) + k] : 0.f;
            __nv_bfloat16 hi, lo; bsplit(v, hi, lo);
            g_W1h[i] = hi; g_W1l[i] = lo;
        }
        {
            int n = i / 288, k = i % 288;
            float v = (k < AF + H) ? Wo[n * (AF + H) + k] : 0.f;
            __nv_bfloat16 hi, lo; bsplit(v, hi, lo);
            g_W2h[i] = hi; g_W2l[i] = lo;
        }
        return;
    }
    b -= WB;
    if (b < CB) {
        long i = (long)b * 256 + threadIdx.x;
        int r = (int)(i / 144), c = (int)(i % 144);
        float v = (r < NN && c < AF) ? __ldg(atom + (size_t)r * AF + c) : 0.f;
        __nv_bfloat16 hi, lo; bsplit(v, hi, lo);
        g_A1h[i] = hi; g_A1l[i] = lo;
        return;
    }
    __shared__ unsigned int s;
    if (threadIdx.x == 0) s = 0;
    __syncthreads();
    unsigned int v = srcw[threadIdx.x * 2 + 1] | srcw[2048 + threadIdx.x * 2 + 1];
    atomicOr(&s, v);
    __syncthreads();
    if (threadIdx.x == 0) g_idx64 = (s == 0u) ? 1 : 0;
}

// ---------------- cvt2: [atom|S3] panel ----------------
__global__ void cvt2(const float* __restrict__ atom, const float* __restrict__ S3) {
    long i = (long)blockIdx.x * blockDim.x + threadIdx.x;
    if (i >= (long)NROWS_PAD * 288) return;
    int r = (int)(i / 288), c = (int)(i % 288);
    float v = 0.f;
    if (r < NN) {
        if (c < AF) v = __ldg(atom + (size_t)r * AF + c);
        else if (c < AF + H) v = __ldg(S3 + (size_t)r * H + (c - AF));
    }
    __nv_bfloat16 hi, lo; bsplit(v, hi, lo);
    g_A2h[i] = hi; g_A2l[i] = lo;
}

// ---------------- node GEMM via mma.sync (proven R6) --------------------------
template<int KPAD, bool RELU>
__global__ __launch_bounds__(512, 1) void ngemm(
    const __nv_bfloat16* __restrict__ Ahg, const __nv_bfloat16* __restrict__ Alg,
    const __nv_bfloat16* __restrict__ Whg, const __nv_bfloat16* __restrict__ Wlg,
    float* __restrict__ out)
{
    extern __shared__ __align__(16) char dyn[];
    __nv_bfloat16* sBh = (__nv_bfloat16*)dyn;
    __nv_bfloat16* sBl = sBh + NGMAT;
    __nv_bfloat16* sAh = sBl + NGMAT;
    __nv_bfloat16* sAl = sAh + NGMAT;

    int tid = threadIdx.x, lane = tid & 31, wid = tid >> 5;
    int m0 = blockIdx.x * 128;
    int wm = (wid >> 2) * 32, wn = (wid & 3) * 32;

    float acc[2][4][4];
    #pragma unroll
    for (int mt = 0; mt < 2; mt++)
        #pragma unroll
        for (int nt = 0; nt < 4; nt++)
            #pragma unroll
            for (int i = 0; i < 4; i++) acc[mt][nt][i] = 0.f;

    const int NCH = KPAD / 144;
    #pragma unroll
    for (int ch = 0; ch < NCH; ch++) {
        if (ch) __syncthreads();
        for (int i = tid; i < 128 * 18; i += 512) {
            int r = i / 18, c = i % 18;
            int go = r * KPAD + ch * 144 + c * 8;
            *(uint4*)(sBh + r * NGS + c * 8) = *(const uint4*)(Whg + go);
            *(uint4*)(sBl + r * NGS + c * 8) = *(const uint4*)(Wlg + go);
        }
        for (int i = tid; i < 128 * 18; i += 512) {
            int r = i / 18, c = i % 18;
            size_t go = (size_t)(m0 + r) * KPAD + ch * 144 + c * 8;
            *(uint4*)(sAh + r * NGS + c * 8) = *(const uint4*)(Ahg + go);
            *(uint4*)(sAl + r * NGS + c * 8) = *(const uint4*)(Alg + go);
        }
        __syncthreads();

        #pragma unroll
        for (int pass = 0; pass < 3; pass++) {
            uint32_t abase = smem_u32(pass == 1 ? sAl : sAh);
            uint32_t bbase = smem_u32(pass == 2 ? sBl : sBh);
            uint32_t aAddr0 = abase + ((uint32_t)(wm + (lane & 15)) * NGS + (lane >> 4) * 8) * 2;
            uint32_t aAddr1 = aAddr0 + 16 * NGS * 2;
            uint32_t bAddr  = bbase + ((uint32_t)(wn + (lane & 7)) * NGS + ((lane >> 3) & 1) * 8) * 2;
            #pragma unroll
            for (int ks = 0; ks < 9; ks++) {
                uint32_t koff = (uint32_t)ks * 32;
                uint32_t a0[4], a1[4];
                ldsm_x4(a0, aAddr0 + koff);
                ldsm_x4(a1, aAddr1 + koff);
                uint32_t b[4][2];
                #pragma unroll
                for (int nt = 0; nt < 4; nt++)
                    ldsm_x2(b[nt], bAddr + (uint32_t)nt * 8 * NGS * 2 + koff);
                #pragma unroll
                for (int nt = 0; nt < 4; nt++) {
                    mma_bf16(acc[0][nt], a0, b[nt]);
                    mma_bf16(acc[1][nt], a1, b[nt]);
                }
            }
        }
    }
    __syncthreads();

    float* sD = (float*)sAh;
    {
        int g = lane >> 2, t2 = (lane & 3) * 2;
        #pragma unroll
        for (int mt = 0; mt < 2; mt++)
            #pragma unroll
            for (int nt = 0; nt < 4; nt++) {
                int r0 = wm + mt * 16 + g, c0 = wn + nt * 8 + t2;
                float2 v0 = make_float2(acc[mt][nt][0], acc[mt][nt][1]);
                float2 v1 = make_float2(acc[mt][nt][2], acc[mt][nt][3]);
                if (RELU) {
                    v0.x = fmaxf(v0.x, 0.f); v0.y = fmaxf(v0.y, 0.f);
                    v1.x = fmaxf(v1.x, 0.f); v1.y = fmaxf(v1.y, 0.f);
                }
                *(float2*)(sD + r0 * SD_STRIDE + c0)       = v0;
                *(float2*)(sD + (r0 + 8) * SD_STRIDE + c0) = v1;
            }
    }
    __syncthreads();
    {
        int row = tid & 127, q = tid >> 7;
        if (m0 + row < NN) {
            const float4* sp = (const float4*)(sD + row * SD_STRIDE + q * 32);
            float* orow = out + (size_t)(m0 + row) * H + q * 32;
            #pragma unroll
            for (int i = 0; i < 8; i++) *(float4*)(orow + i * 4) = sp[i];
        }
    }
}

// ---- initial edge layer: h0 = relu(P[src] + bond @ WbT) (bf16 hi/lo) -------
__global__ __launch_bounds__(256) void init_edges(const float* __restrict__ bond,
                                                  const void* __restrict__ src) {
    __shared__ float sWb[BF * H];
    for (int i = threadIdx.x; i < BF * H; i += 256) sWb[i] = g_WbT[i];
    __syncthreads();
    int warp = threadIdx.x >> 5, lane = threadIdx.x & 31;
    for (long e0 = (long)blockIdx.x * 8; e0 < NE; e0 += (long)gridDim.x * 8) {
        long e = e0 + warp;
        int s = ld_idx(src, e);
        int q = lane * 4;
        float4 acc = *(const float4*)(g_P + (size_t)s * H + q);
        const float* br = bond + e * BF;
        #pragma unroll
        for (int k = 0; k < BF; k++) {
            float b = __ldg(br + k);
            float4 w = *(const float4*)(sWb + k * H + q);
            acc.x += b * w.x; acc.y += b * w.y; acc.z += b * w.z; acc.w += b * w.w;
        }
        acc.x = fmaxf(acc.x, 0.f); acc.y = fmaxf(acc.y, 0.f);
        acc.z = fmaxf(acc.z, 0.f); acc.w = fmaxf(acc.w, 0.f);
        __nv_bfloat16 h0,h1,h2,h3,l0,l1,l2,l3;
        bsplit(acc.x,h0,l0); bsplit(acc.y,h1,l1); bsplit(acc.z,h2,l2); bsplit(acc.w,h3,l3);
        size_t off = (size_t)e * H + q;
        *(uint2*)(g_hh + off) = make_uint2(bpack(h0,h1), bpack(h2,h3));
        *(uint2*)(g_hl + off) = make_uint2(bpack(l0,l1), bpack(l2,l3));
    }
}

// ---------------- edge GEMM: pure streaming (R9-proven), fp16 Y out ----------
__global__ __launch_bounds__(512, 1) void egemm0(
    const __nv_bfloat16* __restrict__ Ah, const __nv_bfloat16* __restrict__ Al,
    const uint4* __restrict__ Bh4,  const uint4* __restrict__ Bl4,
    __half* __restrict__ Yout, float* __restrict__ Sout,
    const void* __restrict__ dstp)
{
    extern __shared__ __align__(16) char dyn[];
    __nv_bfloat16* sBh = (__nv_bfloat16*)dyn;
    __nv_bfloat16* sBl = sBh + BMAT;
    __nv_bfloat16* sSt0 = sBl + BMAT;
    __nv_bfloat16* sSt1 = sSt0 + 2 * BMAT;

    int tid = threadIdx.x, lane = tid & 31, wid = tid >> 5;
    long tile0 = (long)blockIdx.x * TILES_PER_CTA;

    {
        uint32_t st = smem_u32(sSt0);
        long e0 = tile0 * ETILE;
        #pragma unroll
        for (int it = 0; it < 4; it++) {
            int i = tid + it * 512;
            int r = i >> 4, c = i & 15;
            uint32_t doff = (uint32_t)(r * SA_STRIDE + c * 8) * 2;
            cp_async16(st + doff, Ah + (size_t)(e0 + r) * H + c * 8);
            cp_async16(st + (uint32_t)BMAT * 2 + doff, Al + (size_t)(e0 + r) * H + c * 8);
        }
        cp_commit();
    }

    #pragma unroll
    for (int it = 0; it < 4; it++) {
        int i = tid + it * 512;
        int r = i >> 4, c = i & 15;
        *(uint4*)(sBh + r * SA_STRIDE + c * 8) = __ldg(Bh4 + i);
        *(uint4*)(sBl + r * SA_STRIDE + c * 8) = __ldg(Bl4 + i);
    }

    int wm = (wid >> 2) * 32;
    int wn = (wid & 3) * 32;

    for (int t = 0; t < TILES_PER_CTA; t++) {
        long e0 = (tile0 + t) * ETILE;
        __nv_bfloat16* sA = (t & 1) ? sSt1 : sSt0;

        if (t + 1 < TILES_PER_CTA) {
            __nv_bfloat16* nx = (t & 1) ? sSt0 : sSt1;
            uint32_t st = smem_u32(nx);
            long en = (tile0 + t + 1) * ETILE;
            #pragma unroll
            for (int it = 0; it < 4; it++) {
                int i = tid + it * 512;
                int r = i >> 4, c = i & 15;
                uint32_t doff = (uint32_t)(r * SA_STRIDE + c * 8) * 2;
                cp_async16(st + doff, Ah + (size_t)(en + r) * H + c * 8);
                cp_async16(st + (uint32_t)BMAT * 2 + doff, Al + (size_t)(en + r) * H + c * 8);
            }
            cp_commit();
            cp_wait<1>();
        } else {
            cp_wait<0>();
        }
        __syncthreads();

        float acc[2][4][4];
        #pragma unroll
        for (int mt = 0; mt < 2; mt++)
            #pragma unroll
            for (int nt = 0; nt < 4; nt++)
                #pragma unroll
                for (int i = 0; i < 4; i++) acc[mt][nt][i] = 0.f;

        {
            uint32_t aoff = ((uint32_t)(wm + (lane & 15)) * SA_STRIDE + (lane >> 4) * 8) * 2;
            uint32_t boff = ((uint32_t)(wn + (lane & 7)) * SA_STRIDE + ((lane >> 3) & 1) * 8) * 2;
            uint32_t aH = smem_u32(sA) + aoff;
            uint32_t aL = aH + (uint32_t)BMAT * 2;
            uint32_t bH = smem_u32(sBh) + boff;
            uint32_t bL = smem_u32(sBl) + boff;
            const uint32_t rstep = 16 * SA_STRIDE * 2;
            const uint32_t nstep = 8 * SA_STRIDE * 2;
            #pragma unroll
            for (int ks = 0; ks < 8; ks++) {
                uint32_t koff = (uint32_t)ks * 32;
                uint32_t a0h[4], a1h[4], a0l[4], a1l[4];
                ldsm_x4(a0h, aH + koff);
                ldsm_x4(a1h, aH + rstep + koff);
                ldsm_x4(a0l, aL + koff);
                ldsm_x4(a1l, aL + rstep + koff);
                uint32_t bh[4][2], bl[4][2];
                #pragma unroll
                for (int nt = 0; nt < 4; nt++) {
                    ldsm_x2(bh[nt], bH + (uint32_t)nt * nstep + koff);
                    ldsm_x2(bl[nt], bL + (uint32_t)nt * nstep + koff);
                }
                #pragma unroll
                for (int nt = 0; nt < 4; nt++) {
                    mma_bf16(acc[0][nt], a0h, bh[nt]);
                    mma_bf16(acc[1][nt], a1h, bh[nt]);
                    mma_bf16(acc[0][nt], a0l, bh[nt]);
                    mma_bf16(acc[1][nt], a1l, bh[nt]);
                    mma_bf16(acc[0][nt], a0h, bl[nt]);
                    mma_bf16(acc[1][nt], a1h, bl[nt]);
                }
            }
        }
        __syncthreads();

        float* sD = (float*)sA;
        {
            int g = lane >> 2, t2 = (lane & 3) * 2;
            #pragma unroll
            for (int mt = 0; mt < 2; mt++)
                #pragma unroll
                for (int nt = 0; nt < 4; nt++) {
                    int r0 = wm + mt * 16 + g, c0 = wn + nt * 8 + t2;
                    *(float2*)(sD + r0 * SD_STRIDE + c0)       = make_float2(acc[mt][nt][0], acc[mt][nt][1]);
                    *(float2*)(sD + (r0 + 8) * SD_STRIDE + c0) = make_float2(acc[mt][nt][2], acc[mt][nt][3]);
                }
        }
        __syncthreads();

        // epilogue: Y (fp16) write + fp32 red scatter
        {
            int row = tid & 127, q = tid >> 7;
            long e = e0 + row;
            int d = ld_idx(dstp, e);
            const float4* sp = (const float4*)(sD + row * SD_STRIDE + q * 32);
            __half* yrow = Yout + (size_t)e * H + q * 32;
            float* srow = Sout + (size_t)d * H + q * 32;
            #pragma unroll
            for (int i = 0; i < 8; i++) {
                float4 v = sp[i];
                __half2 ha = __floats2half2_rn(v.x, v.y);
                __half2 hb = __floats2half2_rn(v.z, v.w);
                *(uint2*)(yrow + i * 4) = make_uint2(*(uint32_t*)&ha, *(uint32_t*)&hb);
                red4(srow + i * 4, v);
            }
        }
        __syncthreads();
    }
}

// ------- combine1: h = relu(S[src] - Y[rev]) -> g_hh/g_hl (streaming) --------
__global__ __launch_bounds__(256) void combine1(const float* __restrict__ S,
                                                const __half* __restrict__ Yv,
                                                const void* __restrict__ src,
                                                const void* __restrict__ rev) {
    long g = (long)blockIdx.x * 256 + threadIdx.x;
    long e = g >> 5;
    if (e >= NE) return;
    int q = (int)(g & 31) * 4;
    int s = ld_idx(src, e);
    long r = ld_idx(rev, e);
    float4 sv = *(const float4*)(S + (size_t)s * H + q);
    float4 yv = ld_y4(Yv + (size_t)r * H + q);
    float4 h;
    h.x = fmaxf(sv.x - yv.x, 0.f);
    h.y = fmaxf(sv.y - yv.y, 0.f);
    h.z = fmaxf(sv.z - yv.z, 0.f);
    h.w = fmaxf(sv.w - yv.w, 0.f);
    __nv_bfloat16 h0,h1,h2,h3,l0,l1,l2,l3;
    bsplit(h.x,h0,l0); bsplit(h.y,h1,l1); bsplit(h.z,h2,l2); bsplit(h.w,h3,l3);
    size_t off = (size_t)e * H + q;
    *(uint2*)(g_hh + off) = make_uint2(bpack(h0,h1), bpack(h2,h3));
    *(uint2*)(g_hl + off) = make_uint2(bpack(l0,l1), bpack(l2,l3));
}

// ------- combine2: scatter relu(S[src] - Y[rev]) into S3[dst] ----------------
__global__ __launch_bounds__(256) void combine2(const float* __restrict__ S,
                                                const __half* __restrict__ Yv,
                                                const void* __restrict__ src,
                                                const void* __restrict__ rev,
                                                float* __restrict__ S3,
                                                const void* __restrict__ dst) {
    long g = (long)blockIdx.x * 256 + threadIdx.x;
    long e = g >> 5;
    if (e >= NE) return;
    int q = (int)(g & 31) * 4;
    int s = ld_idx(src, e);
    long r = ld_idx(rev, e);
    int d = ld_idx(dst, e);
    float4 sv = *(const float4*)(S + (size_t)s * H + q);
    float4 yv = ld_y4(Yv + (size_t)r * H + q);
    float4 h;
    h.x = fmaxf(sv.x - yv.x, 0.f);
    h.y = fmaxf(sv.y - yv.y, 0.f);
    h.z = fmaxf(sv.z - yv.z, 0.f);
    h.w = fmaxf(sv.w - yv.w, 0.f);
    red4(S3 + (size_t)d * H + q, h);
}

// ---------------- launcher ----------------
extern "C" void kernel_launch(void* const* d_in, const int* in_sizes, int n_in,
                              void* d_out, int out_size) {
    const float* atom = (const float*)d_in[0];
    const float* bond = (const float*)d_in[1];
    const float* Wi   = (const float*)d_in[2];
    const float* Wh   = (const float*)d_in[3];
    const float* Wo   = (const float*)d_in[4];
    const void*  src  = d_in[5];
    const void*  dst  = d_in[6];
    const void*  rev  = d_in[7];
    float* out = (float*)d_out;

    __nv_bfloat16 *hh, *hl, *Bh, *Bl, *W1h, *W1l, *W2h, *W2l, *A1h, *A1l, *A2h, *A2l;
    __half *y1, *y2;
    float *P, *S1, *S2, *S3;
    cudaGetSymbolAddress((void**)&hh, g_hh);
    cudaGetSymbolAddress((void**)&hl, g_hl);
    cudaGetSymbolAddress((void**)&Bh, g_Bh);
    cudaGetSymbolAddress((void**)&Bl, g_Bl);
    cudaGetSymbolAddress((void**)&W1h, g_W1h);
    cudaGetSymbolAddress((void**)&W1l, g_W1l);
    cudaGetSymbolAddress((void**)&W2h, g_W2h);
    cudaGetSymbolAddress((void**)&W2l, g_W2l);
    cudaGetSymbolAddress((void**)&A1h, g_A1h);
    cudaGetSymbolAddress((void**)&A1l, g_A1l);
    cudaGetSymbolAddress((void**)&A2h, g_A2h);
    cudaGetSymbolAddress((void**)&A2l, g_A2l);
    cudaGetSymbolAddress((void**)&y1, g_y1);
    cudaGetSymbolAddress((void**)&y2, g_y2);
    cudaGetSymbolAddress((void**)&P,  g_P);
    cudaGetSymbolAddress((void**)&S1, g_S1);
    cudaGetSymbolAddress((void**)&S2, g_S2);
    cudaGetSymbolAddress((void**)&S3, g_S3);

    const int smemN  = 4 * NGMAT * 2;    // 155648 B
    const int smemE0 = 6 * BMAT * 2;     // 208896 B
    cudaFuncSetAttribute(ngemm<144, false>, cudaFuncAttributeMaxDynamicSharedMemorySize, smemN);
    cudaFuncSetAttribute(ngemm<288, true>,  cudaFuncAttributeMaxDynamicSharedMemorySize, smemN);
    cudaFuncSetAttribute(egemm0, cudaFuncAttributeMaxDynamicSharedMemorySize, smemE0);

    // 1: prep (zeros + weights + atom panel + idx detect)
    prep_all<<<ZB + WB + CB + 1, 256>>>(Wi, Wh, Wo, atom, (const unsigned int*)src,
                                        (float4*)S1, (float4*)S2, (float4*)S3);
    // 2: P = atom @ Wa^T
    ngemm<144, false><<<NGRID, 512, smemN>>>(A1h, A1l, W1h, W1l, P);
    // 3: h0 = relu(P[src] + bond @ WbT)
    init_edges<<<2048, 256>>>(bond, src);
    // 4: iter 1: Y1 = h0 @ Wh^T (fp16 out), scatter S1   (ncu capture slot)
    egemm0<<<EGRID, 512, smemE0>>>(hh, hl, (const uint4*)Bh, (const uint4*)Bl, y1, S1, dst);
    // 5: h1 = relu(S1[src] - Y1[rev])
    combine1<<<NE * 32 / 256, 256>>>(S1, y1, src, rev);
    // 6: iter 2: Y2 = h1 @ Wh^T (fp16 out), scatter S2
    egemm0<<<EGRID, 512, smemE0>>>(hh, hl, (const uint4*)Bh, (const uint4*)Bl, y2, S2, dst);
    // 7: scatter relu(S2[src] - Y2[rev]) into S3
    combine2<<<NE * 32 / 256, 256>>>(S2, y2, src, rev, S3, dst);
    // 8: [atom|S3] panel
    cvt2<<<(int)(((long)NROWS_PAD * 288 + 511) / 512), 512>>>(atom, S3);
    // 9: out = relu([atom|S3] @ Wo^T)
    ngemm<288, true><<<NGRID, 512, smemN>>>(A2h, A2l, W2h, W2l, out);
}

// round 12
// speedup vs baseline: 1.6444x; 1.0893x over previous
#include <cuda_runtime.h>
#include <cuda_bf16.h>
#include <cuda_fp16.h>
#include <cstdint>

#define NN 50000
#define NE 800000
#define AF 133
#define BF 14
#define H  128
#define SA_STRIDE 136
#define SD_STRIDE 132
#define BMAT (128 * SA_STRIDE)          // elems per 128x128 16-bit smem matrix
#define ETILE 128
#define TILES_PER_CTA 5
#define EGRID (NE / ETILE / TILES_PER_CTA)   // 1250

#define NGS  152
#define NGMAT (128 * NGS)
#define NROWS_PAD 50048
#define NGRID 391

// ---------------- scratch ----------------
__device__ __half g_h [(size_t)NE * H];            // edge hidden, single fp16
__device__ __half g_y1[(size_t)NE * H];            // Y in fp16
__device__ __half g_y2[(size_t)NE * H];
__device__ float g_P [(size_t)NN * H];
__device__ float g_S1[(size_t)NN * H];
__device__ float g_S2[(size_t)NN * H];
__device__ float g_S3[(size_t)NN * H];
__device__ float g_WbT[BF * H];
__device__ __half g_Bh[H * H];                     // Wh hi (fp16)  [n][k]
__device__ __half g_Bl[H * H];                     // Wh lo (fp16)
__device__ __nv_bfloat16 g_W1h[128 * 144];
__device__ __nv_bfloat16 g_W1l[128 * 144];
__device__ __nv_bfloat16 g_W2h[128 * 288];
__device__ __nv_bfloat16 g_W2l[128 * 288];
__device__ __nv_bfloat16 g_A1h[(size_t)NROWS_PAD * 144];
__device__ __nv_bfloat16 g_A1l[(size_t)NROWS_PAD * 144];
__device__ __nv_bfloat16 g_A2h[(size_t)NROWS_PAD * 288];
__device__ __nv_bfloat16 g_A2l[(size_t)NROWS_PAD * 288];
__device__ int   g_idx64;

// ---------------- helpers ----------------
__device__ __forceinline__ int ld_idx(const void* p, long i) {
    if (g_idx64) return (int)__ldg((const long long*)p + i);
    return __ldg((const int*)p + i);
}
__device__ __forceinline__ void red4(float* p, float4 v) {
    asm volatile("red.global.add.v4.f32 [%0], {%1,%2,%3,%4};"
                 :: "l"(p), "f"(v.x), "f"(v.y), "f"(v.z), "f"(v.w) : "memory");
}
__device__ __forceinline__ uint32_t smem_u32(const void* p) {
    uint32_t a;
    asm("{ .reg .u64 t; cvta.to.shared.u64 t, %1; cvt.u32.u64 %0, t; }" : "=r"(a) : "l"(p));
    return a;
}
__device__ __forceinline__ void cp_async16(uint32_t sdst, const void* gsrc) {
    asm volatile("cp.async.cg.shared.global [%0], [%1], 16;" :: "r"(sdst), "l"(gsrc) : "memory");
}
__device__ __forceinline__ void cp_commit() {
    asm volatile("cp.async.commit_group;" ::: "memory");
}
template<int N> __device__ __forceinline__ void cp_wait() {
    asm volatile("cp.async.wait_group %0;" :: "n"(N) : "memory");
}
__device__ __forceinline__ void bsplit(float v, __nv_bfloat16& h, __nv_bfloat16& l) {
    h = __float2bfloat16(v);
    l = __float2bfloat16(v - __bfloat162float(h));
}
__device__ __forceinline__ void hsplit(float v, __half& h, __half& l) {
    h = __float2half_rn(v);
    l = __float2half_rn(v - __half2float(h));
}
__device__ __forceinline__ void ldsm_x4(uint32_t (&r)[4], uint32_t addr) {
    asm volatile("ldmatrix.sync.aligned.m8n8.x4.shared.b16 {%0,%1,%2,%3}, [%4];"
                 : "=r"(r[0]), "=r"(r[1]), "=r"(r[2]), "=r"(r[3]) : "r"(addr));
}
__device__ __forceinline__ void ldsm_x2(uint32_t (&r)[2], uint32_t addr) {
    asm volatile("ldmatrix.sync.aligned.m8n8.x2.shared.b16 {%0,%1}, [%2];"
                 : "=r"(r[0]), "=r"(r[1]) : "r"(addr));
}
__device__ __forceinline__ void mma_bf16(float (&d)[4], const uint32_t (&a)[4], const uint32_t (&b)[2]) {
    asm volatile("mma.sync.aligned.m16n8k16.row.col.f32.bf16.bf16.f32 "
                 "{%0,%1,%2,%3}, {%4,%5,%6,%7}, {%8,%9}, {%0,%1,%2,%3};"
                 : "+f"(d[0]), "+f"(d[1]), "+f"(d[2]), "+f"(d[3])
                 : "r"(a[0]), "r"(a[1]), "r"(a[2]), "r"(a[3]), "r"(b[0]), "r"(b[1]));
}
__device__ __forceinline__ void mma_f16(float (&d)[4], const uint32_t (&a)[4], const uint32_t (&b)[2]) {
    asm volatile("mma.sync.aligned.m16n8k16.row.col.f32.f16.f16.f32 "
                 "{%0,%1,%2,%3}, {%4,%5,%6,%7}, {%8,%9}, {%0,%1,%2,%3};"
                 : "+f"(d[0]), "+f"(d[1]), "+f"(d[2]), "+f"(d[3])
                 : "r"(a[0]), "r"(a[1]), "r"(a[2]), "r"(a[3]), "r"(b[0]), "r"(b[1]));
}
__device__ __forceinline__ float4 ld_y4(const __half* p) {
    uint2 raw = __ldg((const uint2*)p);
    __half2 h01 = *(__half2*)&raw.x;
    __half2 h23 = *(__half2*)&raw.y;
    float2 f01 = __half22float2(h01);
    float2 f23 = __half22float2(h23);
    return make_float4(f01.x, f01.y, f23.x, f23.y);
}

// ======= prep_all: zero S bufs | weight prep | atom panel | idx detect ======
#define ZB 18750
#define WB 144
#define CB 28152
__global__ __launch_bounds__(256) void prep_all(
    const float* __restrict__ Wi, const float* __restrict__ Wh,
    const float* __restrict__ Wo, const float* __restrict__ atom,
    const unsigned int* __restrict__ srcw,
    float4* __restrict__ S1, float4* __restrict__ S2, float4* __restrict__ S3)
{
    int b = blockIdx.x;
    if (b < ZB) {
        const long n = (long)NN * H / 4;
        long i = (long)b * 256 + threadIdx.x;
        float4 z = make_float4(0.f, 0.f, 0.f, 0.f);
        if (i < n) S1[i] = z;
        else if (i < 2 * n) S2[i - n] = z;
        else S3[i - 2 * n] = z;
        return;
    }
    b -= ZB;
    if (b < WB) {
        int i = b * 256 + threadIdx.x;
        if (i >= 128 * 288) return;
        if (i < BF * H) {
            int j = i & 127, k = i >> 7;
            g_WbT[i] = Wi[j * (AF + BF) + AF + k];
        }
        if (i < H * H) {                 // Wh split in fp16 (exact hi/lo)
            __half hi, lo; hsplit(Wh[i], hi, lo);
            g_Bh[i] = hi; g_Bl[i] = lo;
        }
        if (i < 128 * 144) {
            int n = i / 144, k = i % 144;
            float v = (k < AF) ? Wi[n * (AF + BF) + k] : 0.f;
            __nv_bfloat16 hi, lo; bsplit(v, hi, lo);
            g_W1h[i] = hi; g_W1l[i] = lo;
        }
        {
            int n = i / 288, k = i % 288;
            float v = (k < AF + H) ? Wo[n * (AF + H) + k] : 0.f;
            __nv_bfloat16 hi, lo; bsplit(v, hi, lo);
            g_W2h[i] = hi; g_W2l[i] = lo;
        }
        return;
    }
    b -= WB;
    if (b < CB) {
        long i = (long)b * 256 + threadIdx.x;
        int r = (int)(i / 144), c = (int)(i % 144);
        float v = (r < NN && c < AF) ? __ldg(atom + (size_t)r * AF + c) : 0.f;
        __nv_bfloat16 hi, lo; bsplit(v, hi, lo);
        g_A1h[i] = hi; g_A1l[i] = lo;
        return;
    }
    __shared__ unsigned int s;
    if (threadIdx.x == 0) s = 0;
    __syncthreads();
    unsigned int v = srcw[threadIdx.x * 2 + 1] | srcw[2048 + threadIdx.x * 2 + 1];
    atomicOr(&s, v);
    __syncthreads();
    if (threadIdx.x == 0) g_idx64 = (s == 0u) ? 1 : 0;
}

// ---------------- cvt2: [atom|S3] panel ----------------
__global__ void cvt2(const float* __restrict__ atom, const float* __restrict__ S3) {
    long i = (long)blockIdx.x * blockDim.x + threadIdx.x;
    if (i >= (long)NROWS_PAD * 288) return;
    int r = (int)(i / 288), c = (int)(i % 288);
    float v = 0.f;
    if (r < NN) {
        if (c < AF) v = __ldg(atom + (size_t)r * AF + c);
        else if (c < AF + H) v = __ldg(S3 + (size_t)r * H + (c - AF));
    }
    __nv_bfloat16 hi, lo; bsplit(v, hi, lo);
    g_A2h[i] = hi; g_A2l[i] = lo;
}

// ---------------- node GEMM via mma.sync (proven R6, bf16 3-pass) ------------
template<int KPAD, bool RELU>
__global__ __launch_bounds__(512, 1) void ngemm(
    const __nv_bfloat16* __restrict__ Ahg, const __nv_bfloat16* __restrict__ Alg,
    const __nv_bfloat16* __restrict__ Whg, const __nv_bfloat16* __restrict__ Wlg,
    float* __restrict__ out)
{
    extern __shared__ __align__(16) char dyn[];
    __nv_bfloat16* sBh = (__nv_bfloat16*)dyn;
    __nv_bfloat16* sBl = sBh + NGMAT;
    __nv_bfloat16* sAh = sBl + NGMAT;
    __nv_bfloat16* sAl = sAh + NGMAT;

    int tid = threadIdx.x, lane = tid & 31, wid = tid >> 5;
    int m0 = blockIdx.x * 128;
    int wm = (wid >> 2) * 32, wn = (wid & 3) * 32;

    float acc[2][4][4];
    #pragma unroll
    for (int mt = 0; mt < 2; mt++)
        #pragma unroll
        for (int nt = 0; nt < 4; nt++)
            #pragma unroll
            for (int i = 0; i < 4; i++) acc[mt][nt][i] = 0.f;

    const int NCH = KPAD / 144;
    #pragma unroll
    for (int ch = 0; ch < NCH; ch++) {
        if (ch) __syncthreads();
        for (int i = tid; i < 128 * 18; i += 512) {
            int r = i / 18, c = i % 18;
            int go = r * KPAD + ch * 144 + c * 8;
            *(uint4*)(sBh + r * NGS + c * 8) = *(const uint4*)(Whg + go);
            *(uint4*)(sBl + r * NGS + c * 8) = *(const uint4*)(Wlg + go);
        }
        for (int i = tid; i < 128 * 18; i += 512) {
            int r = i / 18, c = i % 18;
            size_t go = (size_t)(m0 + r) * KPAD + ch * 144 + c * 8;
            *(uint4*)(sAh + r * NGS + c * 8) = *(const uint4*)(Ahg + go);
            *(uint4*)(sAl + r * NGS + c * 8) = *(const uint4*)(Alg + go);
        }
        __syncthreads();

        #pragma unroll
        for (int pass = 0; pass < 3; pass++) {
            uint32_t abase = smem_u32(pass == 1 ? sAl : sAh);
            uint32_t bbase = smem_u32(pass == 2 ? sBl : sBh);
            uint32_t aAddr0 = abase + ((uint32_t)(wm + (lane & 15)) * NGS + (lane >> 4) * 8) * 2;
            uint32_t aAddr1 = aAddr0 + 16 * NGS * 2;
            uint32_t bAddr  = bbase + ((uint32_t)(wn + (lane & 7)) * NGS + ((lane >> 3) & 1) * 8) * 2;
            #pragma unroll
            for (int ks = 0; ks < 9; ks++) {
                uint32_t koff = (uint32_t)ks * 32;
                uint32_t a0[4], a1[4];
                ldsm_x4(a0, aAddr0 + koff);
                ldsm_x4(a1, aAddr1 + koff);
                uint32_t b[4][2];
                #pragma unroll
                for (int nt = 0; nt < 4; nt++)
                    ldsm_x2(b[nt], bAddr + (uint32_t)nt * 8 * NGS * 2 + koff);
                #pragma unroll
                for (int nt = 0; nt < 4; nt++) {
                    mma_bf16(acc[0][nt], a0, b[nt]);
                    mma_bf16(acc[1][nt], a1, b[nt]);
                }
            }
        }
    }
    __syncthreads();

    float* sD = (float*)sAh;
    {
        int g = lane >> 2, t2 = (lane & 3) * 2;
        #pragma unroll
        for (int mt = 0; mt < 2; mt++)
            #pragma unroll
            for (int nt = 0; nt < 4; nt++) {
                int r0 = wm + mt * 16 + g, c0 = wn + nt * 8 + t2;
                float2 v0 = make_float2(acc[mt][nt][0], acc[mt][nt][1]);
                float2 v1 = make_float2(acc[mt][nt][2], acc[mt][nt][3]);
                if (RELU) {
                    v0.x = fmaxf(v0.x, 0.f); v0.y = fmaxf(v0.y, 0.f);
                    v1.x = fmaxf(v1.x, 0.f); v1.y = fmaxf(v1.y, 0.f);
                }
                *(float2*)(sD + r0 * SD_STRIDE + c0)       = v0;
                *(float2*)(sD + (r0 + 8) * SD_STRIDE + c0) = v1;
            }
    }
    __syncthreads();
    {
        int row = tid & 127, q = tid >> 7;
        if (m0 + row < NN) {
            const float4* sp = (const float4*)(sD + row * SD_STRIDE + q * 32);
            float* orow = out + (size_t)(m0 + row) * H + q * 32;
            #pragma unroll
            for (int i = 0; i < 8; i++) *(float4*)(orow + i * 4) = sp[i];
        }
    }
}

// ---- initial edge layer: h0 = relu(P[src] + bond @ WbT) (fp16) -------------
__global__ __launch_bounds__(256) void init_edges(const float* __restrict__ bond,
                                                  const void* __restrict__ src) {
    __shared__ float sWb[BF * H];
    for (int i = threadIdx.x; i < BF * H; i += 256) sWb[i] = g_WbT[i];
    __syncthreads();
    int warp = threadIdx.x >> 5, lane = threadIdx.x & 31;
    for (long e0 = (long)blockIdx.x * 8; e0 < NE; e0 += (long)gridDim.x * 8) {
        long e = e0 + warp;
        int s = ld_idx(src, e);
        int q = lane * 4;
        float4 acc = *(const float4*)(g_P + (size_t)s * H + q);
        const float* br = bond + e * BF;
        #pragma unroll
        for (int k = 0; k < BF; k++) {
            float b = __ldg(br + k);
            float4 w = *(const float4*)(sWb + k * H + q);
            acc.x += b * w.x; acc.y += b * w.y; acc.z += b * w.z; acc.w += b * w.w;
        }
        acc.x = fmaxf(acc.x, 0.f); acc.y = fmaxf(acc.y, 0.f);
        acc.z = fmaxf(acc.z, 0.f); acc.w = fmaxf(acc.w, 0.f);
        __half2 p0 = __floats2half2_rn(acc.x, acc.y);
        __half2 p1 = __floats2half2_rn(acc.z, acc.w);
        *(uint2*)(g_h + (size_t)e * H + q) = make_uint2(*(uint32_t*)&p0, *(uint32_t*)&p1);
    }
}

// ---------------- edge GEMM: streaming fp16 A, 2-pass fp16 mma ---------------
// smem layout: B hi | B lo | A stage0 | A stage1 | D staging (dedicated).
__global__ __launch_bounds__(512, 1) void egemm0(
    const __half* __restrict__ Ag,
    const uint4* __restrict__ Bh4,  const uint4* __restrict__ Bl4,
    __half* __restrict__ Yout, float* __restrict__ Sout,
    const void* __restrict__ dstp)
{
    extern __shared__ __align__(16) char dyn[];
    __half* sBh = (__half*)dyn;
    __half* sBl = sBh + BMAT;
    __half* sSt0 = sBl + BMAT;          // single-matrix A stage
    __half* sSt1 = sSt0 + BMAT;
    float* sD = (float*)(sSt1 + BMAT);  // dedicated 128*SD_STRIDE fp32 staging

    int tid = threadIdx.x, lane = tid & 31, wid = tid >> 5;
    long tile0 = (long)blockIdx.x * TILES_PER_CTA;

    // prefetch tile 0 (fp16 A: 2048 x 16B chunks)
    {
        uint32_t st = smem_u32(sSt0);
        long e0 = tile0 * ETILE;
        #pragma unroll
        for (int it = 0; it < 4; it++) {
            int i = tid + it * 512;
            int r = i >> 4, c = i & 15;
            cp_async16(st + (uint32_t)(r * SA_STRIDE + c * 8) * 2,
                       Ag + (size_t)(e0 + r) * H + c * 8);
        }
        cp_commit();
    }

    // B (hi/lo) resident
    #pragma unroll
    for (int it = 0; it < 4; it++) {
        int i = tid + it * 512;
        int r = i >> 4, c = i & 15;
        *(uint4*)(sBh + r * SA_STRIDE + c * 8) = __ldg(Bh4 + i);
        *(uint4*)(sBl + r * SA_STRIDE + c * 8) = __ldg(Bl4 + i);
    }

    int wm = (wid >> 2) * 32;
    int wn = (wid & 3) * 32;

    for (int t = 0; t < TILES_PER_CTA; t++) {
        long e0 = (tile0 + t) * ETILE;
        __half* sA = (t & 1) ? sSt1 : sSt0;

        // issue prefetch(t+1) into other stage FIRST, then drain tile t
        if (t + 1 < TILES_PER_CTA) {
            __half* nx = (t & 1) ? sSt0 : sSt1;
            uint32_t st = smem_u32(nx);
            long en = (tile0 + t + 1) * ETILE;
            #pragma unroll
            for (int it = 0; it < 4; it++) {
                int i = tid + it * 512;
                int r = i >> 4, c = i & 15;
                cp_async16(st + (uint32_t)(r * SA_STRIDE + c * 8) * 2,
                           Ag + (size_t)(en + r) * H + c * 8);
            }
            cp_commit();
            cp_wait<1>();
        } else {
            cp_wait<0>();
        }
        __syncthreads();

        float acc[2][4][4];
        #pragma unroll
        for (int mt = 0; mt < 2; mt++)
            #pragma unroll
            for (int nt = 0; nt < 4; nt++)
                #pragma unroll
                for (int i = 0; i < 4; i++) acc[mt][nt][i] = 0.f;

        {
            uint32_t aoff = ((uint32_t)(wm + (lane & 15)) * SA_STRIDE + (lane >> 4) * 8) * 2;
            uint32_t boff = ((uint32_t)(wn + (lane & 7)) * SA_STRIDE + ((lane >> 3) & 1) * 8) * 2;
            uint32_t aA = smem_u32(sA) + aoff;
            uint32_t bH = smem_u32(sBh) + boff;
            uint32_t bL = smem_u32(sBl) + boff;
            const uint32_t rstep = 16 * SA_STRIDE * 2;
            const uint32_t nstep = 8 * SA_STRIDE * 2;
            #pragma unroll
            for (int ks = 0; ks < 8; ks++) {
                uint32_t koff = (uint32_t)ks * 32;
                uint32_t a0[4], a1[4];
                ldsm_x4(a0, aA + koff);
                ldsm_x4(a1, aA + rstep + koff);
                uint32_t bh[4][2], bl[4][2];
                #pragma unroll
                for (int nt = 0; nt < 4; nt++) {
                    ldsm_x2(bh[nt], bH + (uint32_t)nt * nstep + koff);
                    ldsm_x2(bl[nt], bL + (uint32_t)nt * nstep + koff);
                }
                #pragma unroll
                for (int nt = 0; nt < 4; nt++) {
                    mma_f16(acc[0][nt], a0, bh[nt]);
                    mma_f16(acc[1][nt], a1, bh[nt]);
                    mma_f16(acc[0][nt], a0, bl[nt]);
                    mma_f16(acc[1][nt], a1, bl[nt]);
                }
            }
        }
        __syncthreads();

        // D staging (fp32) in DEDICATED region — no overlap with A stages
        {
            int g = lane >> 2, t2 = (lane & 3) * 2;
            #pragma unroll
            for (int mt = 0; mt < 2; mt++)
                #pragma unroll
                for (int nt = 0; nt < 4; nt++) {
                    int r0 = wm + mt * 16 + g, c0 = wn + nt * 8 + t2;
                    *(float2*)(sD + r0 * SD_STRIDE + c0)       = make_float2(acc[mt][nt][0], acc[mt][nt][1]);
                    *(float2*)(sD + (r0 + 8) * SD_STRIDE + c0) = make_float2(acc[mt][nt][2], acc[mt][nt][3]);
                }
        }
        __syncthreads();

        // epilogue: Y (fp16) write + fp32 red scatter
        {
            int row = tid & 127, q = tid >> 7;
            long e = e0 + row;
            int d = ld_idx(dstp, e);
            const float4* sp = (const float4*)(sD + row * SD_STRIDE + q * 32);
            __half* yrow = Yout + (size_t)e * H + q * 32;
            float* srow = Sout + (size_t)d * H + q * 32;
            #pragma unroll
            for (int i = 0; i < 8; i++) {
                float4 v = sp[i];
                __half2 ha = __floats2half2_rn(v.x, v.y);
                __half2 hb = __floats2half2_rn(v.z, v.w);
                *(uint2*)(yrow + i * 4) = make_uint2(*(uint32_t*)&ha, *(uint32_t*)&hb);
                red4(srow + i * 4, v);
            }
        }
        __syncthreads();
    }
}

// ------- combine1: h = relu(S[src] - Y[rev]) -> g_h (fp16, streaming) --------
__global__ __launch_bounds__(256) void combine1(const float* __restrict__ S,
                                                const __half* __restrict__ Yv,
                                                const void* __restrict__ src,
                                                const void* __restrict__ rev) {
    long g = (long)blockIdx.x * 256 + threadIdx.x;
    long e = g >> 5;
    if (e >= NE) return;
    int q = (int)(g & 31) * 4;
    int s = ld_idx(src, e);
    long r = ld_idx(rev, e);
    float4 sv = *(const float4*)(S + (size_t)s * H + q);
    float4 yv = ld_y4(Yv + (size_t)r * H + q);
    float4 h;
    h.x = fmaxf(sv.x - yv.x, 0.f);
    h.y = fmaxf(sv.y - yv.y, 0.f);
    h.z = fmaxf(sv.z - yv.z, 0.f);
    h.w = fmaxf(sv.w - yv.w, 0.f);
    __half2 p0 = __floats2half2_rn(h.x, h.y);
    __half2 p1 = __floats2half2_rn(h.z, h.w);
    *(uint2*)(g_h + (size_t)e * H + q) = make_uint2(*(uint32_t*)&p0, *(uint32_t*)&p1);
}

// ------- combine2: scatter relu(S[src] - Y[rev]) into S3[dst] ----------------
__global__ __launch_bounds__(256) void combine2(const float* __restrict__ S,
                                                const __half* __restrict__ Yv,
                                                const void* __restrict__ src,
                                                const void* __restrict__ rev,
                                                float* __restrict__ S3,
                                                const void* __restrict__ dst) {
    long g = (long)blockIdx.x * 256 + threadIdx.x;
    long e = g >> 5;
    if (e >= NE) return;
    int q = (int)(g & 31) * 4;
    int s = ld_idx(src, e);
    long r = ld_idx(rev, e);
    int d = ld_idx(dst, e);
    float4 sv = *(const float4*)(S + (size_t)s * H + q);
    float4 yv = ld_y4(Yv + (size_t)r * H + q);
    float4 h;
    h.x = fmaxf(sv.x - yv.x, 0.f);
    h.y = fmaxf(sv.y - yv.y, 0.f);
    h.z = fmaxf(sv.z - yv.z, 0.f);
    h.w = fmaxf(sv.w - yv.w, 0.f);
    red4(S3 + (size_t)d * H + q, h);
}

// ---------------- launcher ----------------
extern "C" void kernel_launch(void* const* d_in, const int* in_sizes, int n_in,
                              void* d_out, int out_size) {
    const float* atom = (const float*)d_in[0];
    const float* bond = (const float*)d_in[1];
    const float* Wi   = (const float*)d_in[2];
    const float* Wh   = (const float*)d_in[3];
    const float* Wo   = (const float*)d_in[4];
    const void*  src  = d_in[5];
    const void*  dst  = d_in[6];
    const void*  rev  = d_in[7];
    float* out = (float*)d_out;

    __nv_bfloat16 *W1h, *W1l, *W2h, *W2l, *A1h, *A1l, *A2h, *A2l;
    __half *h, *y1, *y2, *Bh, *Bl;
    float *P, *S1, *S2, *S3;
    cudaGetSymbolAddress((void**)&h,  g_h);
    cudaGetSymbolAddress((void**)&Bh, g_Bh);
    cudaGetSymbolAddress((void**)&Bl, g_Bl);
    cudaGetSymbolAddress((void**)&W1h, g_W1h);
    cudaGetSymbolAddress((void**)&W1l, g_W1l);
    cudaGetSymbolAddress((void**)&W2h, g_W2h);
    cudaGetSymbolAddress((void**)&W2l, g_W2l);
    cudaGetSymbolAddress((void**)&A1h, g_A1h);
    cudaGetSymbolAddress((void**)&A1l, g_A1l);
    cudaGetSymbolAddress((void**)&A2h, g_A2h);
    cudaGetSymbolAddress((void**)&A2l, g_A2l);
    cudaGetSymbolAddress((void**)&y1, g_y1);
    cudaGetSymbolAddress((void**)&y2, g_y2);
    cudaGetSymbolAddress((void**)&P,  g_P);
    cudaGetSymbolAddress((void**)&S1, g_S1);
    cudaGetSymbolAddress((void**)&S2, g_S2);
    cudaGetSymbolAddress((void**)&S3, g_S3);

    const int smemN  = 4 * NGMAT * 2;                        // 155648 B
    const int smemE0 = 4 * BMAT * 2 + 128 * SD_STRIDE * 4;   // 139264 + 67584 = 206848 B
    cudaFuncSetAttribute(ngemm<144, false>, cudaFuncAttributeMaxDynamicSharedMemorySize, smemN);
    cudaFuncSetAttribute(ngemm<288, true>,  cudaFuncAttributeMaxDynamicSharedMemorySize, smemN);
    cudaFuncSetAttribute(egemm0, cudaFuncAttributeMaxDynamicSharedMemorySize, smemE0);

    // 1: prep (zeros + weights + atom panel + idx detect)
    prep_all<<<ZB + WB + CB + 1, 256>>>(Wi, Wh, Wo, atom, (const unsigned int*)src,
                                        (float4*)S1, (float4*)S2, (float4*)S3);
    // 2: P = atom @ Wa^T
    ngemm<144, false><<<NGRID, 512, smemN>>>(A1h, A1l, W1h, W1l, P);
    // 3: h0 = relu(P[src] + bond @ WbT)  (fp16)
    init_edges<<<2048, 256>>>(bond, src);
    // 4: iter 1: Y1 = h0 @ Wh^T (2-pass fp16), scatter S1   (ncu capture slot)
    egemm0<<<EGRID, 512, smemE0>>>(h, (const uint4*)Bh, (const uint4*)Bl, y1, S1, dst);
    // 5: h1 = relu(S1[src] - Y1[rev])  (fp16)
    combine1<<<NE * 32 / 256, 256>>>(S1, y1, src, rev);
    // 6: iter 2: Y2 = h1 @ Wh^T, scatter S2
    egemm0<<<EGRID, 512, smemE0>>>(h, (const uint4*)Bh, (const uint4*)Bl, y2, S2, dst);
    // 7: scatter relu(S2[src] - Y2[rev]) into S3
    combine2<<<NE * 32 / 256, 256>>>(S2, y2, src, rev, S3, dst);
    // 8: [atom|S3] panel
    cvt2<<<(int)(((long)NROWS_PAD * 288 + 511) / 512), 512>>>(atom, S3);
    // 9: out = relu([atom|S3] @ Wo^T)
    ngemm<288, true><<<NGRID, 512, smemN>>>(A2h, A2l, W2h, W2l, out);
}

// round 13
// speedup vs baseline: 1.9196x; 1.1674x over previous
#include <cuda_runtime.h>
#include <cuda_fp16.h>
#include <cstdint>

#define NN 50000
#define NE 800000
#define AF 133
#define BF 14
#define H  128
#define SA_STRIDE 136
#define SD_STRIDE 132
#define BMAT (128 * SA_STRIDE)          // elems per 128x128 16-bit smem matrix
#define ETILE 128
#define TILES_PER_CTA 5
#define EGRID (NE / ETILE / TILES_PER_CTA)   // 1250

#define NGS  152
#define NGMAT (128 * NGS)
#define NROWS_PAD 50048
#define NGRID 391

// ---------------- scratch ----------------
__device__ __half g_h [(size_t)NE * H];            // edge hidden (fp16)
__device__ __half g_y1[(size_t)NE * H];            // Y (fp16)
__device__ __half g_y2[(size_t)NE * H];
__device__ float g_P [(size_t)NN * H];
__device__ float g_S1[(size_t)NN * H];
__device__ float g_S2[(size_t)NN * H];
__device__ float g_S3[(size_t)NN * H];
__device__ float g_WbT[BF * H];
__device__ __half g_B [H * H];                     // Wh (fp16)  [n][k]
__device__ __half g_W1[128 * 144];                 // Wa padded (fp16) [n][k]
__device__ __half g_W2[128 * 288];                 // Wo padded (fp16) [n][k]
__device__ __half g_A1[(size_t)NROWS_PAD * 144];   // atom panel (fp16)
__device__ __half g_A2[(size_t)NROWS_PAD * 288];   // [atom|S3] panel (fp16)
__device__ int   g_idx64;

// ---------------- helpers ----------------
__device__ __forceinline__ int ld_idx(const void* p, long i) {
    if (g_idx64) return (int)__ldg((const long long*)p + i);
    return __ldg((const int*)p + i);
}
__device__ __forceinline__ void red4(float* p, float4 v) {
    asm volatile("red.global.add.v4.f32 [%0], {%1,%2,%3,%4};"
                 :: "l"(p), "f"(v.x), "f"(v.y), "f"(v.z), "f"(v.w) : "memory");
}
__device__ __forceinline__ uint32_t smem_u32(const void* p) {
    uint32_t a;
    asm("{ .reg .u64 t; cvta.to.shared.u64 t, %1; cvt.u32.u64 %0, t; }" : "=r"(a) : "l"(p));
    return a;
}
__device__ __forceinline__ void cp_async16(uint32_t sdst, const void* gsrc) {
    asm volatile("cp.async.cg.shared.global [%0], [%1], 16;" :: "r"(sdst), "l"(gsrc) : "memory");
}
__device__ __forceinline__ void cp_commit() {
    asm volatile("cp.async.commit_group;" ::: "memory");
}
template<int N> __device__ __forceinline__ void cp_wait() {
    asm volatile("cp.async.wait_group %0;" :: "n"(N) : "memory");
}
__device__ __forceinline__ void ldsm_x4(uint32_t (&r)[4], uint32_t addr) {
    asm volatile("ldmatrix.sync.aligned.m8n8.x4.shared.b16 {%0,%1,%2,%3}, [%4];"
                 : "=r"(r[0]), "=r"(r[1]), "=r"(r[2]), "=r"(r[3]) : "r"(addr));
}
__device__ __forceinline__ void ldsm_x2(uint32_t (&r)[2], uint32_t addr) {
    asm volatile("ldmatrix.sync.aligned.m8n8.x2.shared.b16 {%0,%1}, [%2];"
                 : "=r"(r[0]), "=r"(r[1]) : "r"(addr));
}
__device__ __forceinline__ void mma_f16(float (&d)[4], const uint32_t (&a)[4], const uint32_t (&b)[2]) {
    asm volatile("mma.sync.aligned.m16n8k16.row.col.f32.f16.f16.f32 "
                 "{%0,%1,%2,%3}, {%4,%5,%6,%7}, {%8,%9}, {%0,%1,%2,%3};"
                 : "+f"(d[0]), "+f"(d[1]), "+f"(d[2]), "+f"(d[3])
                 : "r"(a[0]), "r"(a[1]), "r"(a[2]), "r"(a[3]), "r"(b[0]), "r"(b[1]));
}
__device__ __forceinline__ float4 ld_y4(const __half* p) {
    uint2 raw = __ldg((const uint2*)p);
    __half2 h01 = *(__half2*)&raw.x;
    __half2 h23 = *(__half2*)&raw.y;
    float2 f01 = __half22float2(h01);
    float2 f23 = __half22float2(h23);
    return make_float4(f01.x, f01.y, f23.x, f23.y);
}

// ======= prep_all: zero S bufs | weight prep | atom panel | idx detect ======
#define ZB 18750
#define WB 144
#define CB 28152
__global__ __launch_bounds__(256) void prep_all(
    const float* __restrict__ Wi, const float* __restrict__ Wh,
    const float* __restrict__ Wo, const float* __restrict__ atom,
    const unsigned int* __restrict__ srcw,
    float4* __restrict__ S1, float4* __restrict__ S2, float4* __restrict__ S3)
{
    int b = blockIdx.x;
    if (b < ZB) {
        const long n = (long)NN * H / 4;
        long i = (long)b * 256 + threadIdx.x;
        float4 z = make_float4(0.f, 0.f, 0.f, 0.f);
        if (i < n) S1[i] = z;
        else if (i < 2 * n) S2[i - n] = z;
        else S3[i - 2 * n] = z;
        return;
    }
    b -= ZB;
    if (b < WB) {
        int i = b * 256 + threadIdx.x;
        if (i >= 128 * 288) return;
        if (i < BF * H) {
            int j = i & 127, k = i >> 7;
            g_WbT[i] = Wi[j * (AF + BF) + AF + k];
        }
        if (i < H * H)
            g_B[i] = __float2half_rn(Wh[i]);
        if (i < 128 * 144) {
            int n = i / 144, k = i % 144;
            g_W1[i] = __float2half_rn((k < AF) ? Wi[n * (AF + BF) + k] : 0.f);
        }
        {
            int n = i / 288, k = i % 288;
            g_W2[i] = __float2half_rn((k < AF + H) ? Wo[n * (AF + H) + k] : 0.f);
        }
        return;
    }
    b -= WB;
    if (b < CB) {
        long i = (long)b * 256 + threadIdx.x;
        int r = (int)(i / 144), c = (int)(i % 144);
        float v = (r < NN && c < AF) ? __ldg(atom + (size_t)r * AF + c) : 0.f;
        g_A1[i] = __float2half_rn(v);
        return;
    }
    __shared__ unsigned int s;
    if (threadIdx.x == 0) s = 0;
    __syncthreads();
    unsigned int v = srcw[threadIdx.x * 2 + 1] | srcw[2048 + threadIdx.x * 2 + 1];
    atomicOr(&s, v);
    __syncthreads();
    if (threadIdx.x == 0) g_idx64 = (s == 0u) ? 1 : 0;
}

// ---------------- cvt2: [atom|S3] panel (fp16) ----------------
__global__ void cvt2(const float* __restrict__ atom, const float* __restrict__ S3) {
    long i = (long)blockIdx.x * blockDim.x + threadIdx.x;
    if (i >= (long)NROWS_PAD * 288) return;
    int r = (int)(i / 288), c = (int)(i % 288);
    float v = 0.f;
    if (r < NN) {
        if (c < AF) v = __ldg(atom + (size_t)r * AF + c);
        else if (c < AF + H) v = __ldg(S3 + (size_t)r * H + (c - AF));
    }
    g_A2[i] = __float2half_rn(v);
}

// ---------------- node GEMM via mma.sync (single fp16, 1 pass) ---------------
template<int KPAD, bool RELU>
__global__ __launch_bounds__(512, 1) void ngemm(
    const __half* __restrict__ Ag, const __half* __restrict__ Wg,
    float* __restrict__ out)
{
    extern __shared__ __align__(16) char dyn[];
    __half* sB = (__half*)dyn;
    __half* sA = sB + NGMAT;
    float*  sD = (float*)(sA + NGMAT);   // dedicated staging

    int tid = threadIdx.x, lane = tid & 31, wid = tid >> 5;
    int m0 = blockIdx.x * 128;
    int wm = (wid >> 2) * 32, wn = (wid & 3) * 32;

    float acc[2][4][4];
    #pragma unroll
    for (int mt = 0; mt < 2; mt++)
        #pragma unroll
        for (int nt = 0; nt < 4; nt++)
            #pragma unroll
            for (int i = 0; i < 4; i++) acc[mt][nt][i] = 0.f;

    const int NCH = KPAD / 144;
    #pragma unroll
    for (int ch = 0; ch < NCH; ch++) {
        if (ch) __syncthreads();
        for (int i = tid; i < 128 * 18; i += 512) {
            int r = i / 18, c = i % 18;
            int go = r * KPAD + ch * 144 + c * 8;
            *(uint4*)(sB + r * NGS + c * 8) = *(const uint4*)(Wg + go);
        }
        for (int i = tid; i < 128 * 18; i += 512) {
            int r = i / 18, c = i % 18;
            size_t go = (size_t)(m0 + r) * KPAD + ch * 144 + c * 8;
            *(uint4*)(sA + r * NGS + c * 8) = *(const uint4*)(Ag + go);
        }
        __syncthreads();

        uint32_t aAddr0 = smem_u32(sA) + ((uint32_t)(wm + (lane & 15)) * NGS + (lane >> 4) * 8) * 2;
        uint32_t aAddr1 = aAddr0 + 16 * NGS * 2;
        uint32_t bAddr  = smem_u32(sB) + ((uint32_t)(wn + (lane & 7)) * NGS + ((lane >> 3) & 1) * 8) * 2;
        #pragma unroll
        for (int ks = 0; ks < 9; ks++) {
            uint32_t koff = (uint32_t)ks * 32;
            uint32_t a0[4], a1[4];
            ldsm_x4(a0, aAddr0 + koff);
            ldsm_x4(a1, aAddr1 + koff);
            uint32_t b[4][2];
            #pragma unroll
            for (int nt = 0; nt < 4; nt++)
                ldsm_x2(b[nt], bAddr + (uint32_t)nt * 8 * NGS * 2 + koff);
            #pragma unroll
            for (int nt = 0; nt < 4; nt++) {
                mma_f16(acc[0][nt], a0, b[nt]);
                mma_f16(acc[1][nt], a1, b[nt]);
            }
        }
    }
    __syncthreads();

    {
        int g = lane >> 2, t2 = (lane & 3) * 2;
        #pragma unroll
        for (int mt = 0; mt < 2; mt++)
            #pragma unroll
            for (int nt = 0; nt < 4; nt++) {
                int r0 = wm + mt * 16 + g, c0 = wn + nt * 8 + t2;
                float2 v0 = make_float2(acc[mt][nt][0], acc[mt][nt][1]);
                float2 v1 = make_float2(acc[mt][nt][2], acc[mt][nt][3]);
                if (RELU) {
                    v0.x = fmaxf(v0.x, 0.f); v0.y = fmaxf(v0.y, 0.f);
                    v1.x = fmaxf(v1.x, 0.f); v1.y = fmaxf(v1.y, 0.f);
                }
                *(float2*)(sD + r0 * SD_STRIDE + c0)       = v0;
                *(float2*)(sD + (r0 + 8) * SD_STRIDE + c0) = v1;
            }
    }
    __syncthreads();
    {
        int row = tid & 127, q = tid >> 7;
        if (m0 + row < NN) {
            const float4* sp = (const float4*)(sD + row * SD_STRIDE + q * 32);
            float* orow = out + (size_t)(m0 + row) * H + q * 32;
            #pragma unroll
            for (int i = 0; i < 8; i++) *(float4*)(orow + i * 4) = sp[i];
        }
    }
}

// ---- initial edge layer: h0 = relu(P[src] + bond @ WbT) (fp16) -------------
__global__ __launch_bounds__(256) void init_edges(const float* __restrict__ bond,
                                                  const void* __restrict__ src) {
    __shared__ float sWb[BF * H];
    for (int i = threadIdx.x; i < BF * H; i += 256) sWb[i] = g_WbT[i];
    __syncthreads();
    int warp = threadIdx.x >> 5, lane = threadIdx.x & 31;
    for (long e0 = (long)blockIdx.x * 8; e0 < NE; e0 += (long)gridDim.x * 8) {
        long e = e0 + warp;
        int s = ld_idx(src, e);
        int q = lane * 4;
        float4 acc = *(const float4*)(g_P + (size_t)s * H + q);
        const float* br = bond + e * BF;
        #pragma unroll
        for (int k = 0; k < BF; k++) {
            float b = __ldg(br + k);
            float4 w = *(const float4*)(sWb + k * H + q);
            acc.x += b * w.x; acc.y += b * w.y; acc.z += b * w.z; acc.w += b * w.w;
        }
        acc.x = fmaxf(acc.x, 0.f); acc.y = fmaxf(acc.y, 0.f);
        acc.z = fmaxf(acc.z, 0.f); acc.w = fmaxf(acc.w, 0.f);
        __half2 p0 = __floats2half2_rn(acc.x, acc.y);
        __half2 p1 = __floats2half2_rn(acc.z, acc.w);
        *(uint2*)(g_h + (size_t)e * H + q) = make_uint2(*(uint32_t*)&p0, *(uint32_t*)&p1);
    }
}

// ---------------- edge GEMM: streaming fp16 A, single-pass fp16 mma ----------
// smem: B | A stage0 | A stage1 | D staging (dedicated).
__global__ __launch_bounds__(512, 1) void egemm0(
    const __half* __restrict__ Ag,
    const uint4* __restrict__ B4,
    __half* __restrict__ Yout, float* __restrict__ Sout,
    const void* __restrict__ dstp)
{
    extern __shared__ __align__(16) char dyn[];
    __half* sB = (__half*)dyn;
    __half* sSt0 = sB + BMAT;
    __half* sSt1 = sSt0 + BMAT;
    float* sD = (float*)(sSt1 + BMAT);   // dedicated fp32 staging

    int tid = threadIdx.x, lane = tid & 31, wid = tid >> 5;
    long tile0 = (long)blockIdx.x * TILES_PER_CTA;

    // prefetch tile 0
    {
        uint32_t st = smem_u32(sSt0);
        long e0 = tile0 * ETILE;
        #pragma unroll
        for (int it = 0; it < 4; it++) {
            int i = tid + it * 512;
            int r = i >> 4, c = i & 15;
            cp_async16(st + (uint32_t)(r * SA_STRIDE + c * 8) * 2,
                       Ag + (size_t)(e0 + r) * H + c * 8);
        }
        cp_commit();
    }

    // B resident
    #pragma unroll
    for (int it = 0; it < 4; it++) {
        int i = tid + it * 512;
        int r = i >> 4, c = i & 15;
        *(uint4*)(sB + r * SA_STRIDE + c * 8) = __ldg(B4 + i);
    }

    int wm = (wid >> 2) * 32;
    int wn = (wid & 3) * 32;

    for (int t = 0; t < TILES_PER_CTA; t++) {
        long e0 = (tile0 + t) * ETILE;
        __half* sA = (t & 1) ? sSt1 : sSt0;

        // issue prefetch(t+1) FIRST, then drain tile t
        if (t + 1 < TILES_PER_CTA) {
            __half* nx = (t & 1) ? sSt0 : sSt1;
            uint32_t st = smem_u32(nx);
            long en = (tile0 + t + 1) * ETILE;
            #pragma unroll
            for (int it = 0; it < 4; it++) {
                int i = tid + it * 512;
                int r = i >> 4, c = i & 15;
                cp_async16(st + (uint32_t)(r * SA_STRIDE + c * 8) * 2,
                           Ag + (size_t)(en + r) * H + c * 8);
            }
            cp_commit();
            cp_wait<1>();
        } else {
            cp_wait<0>();
        }
        __syncthreads();

        float acc[2][4][4];
        #pragma unroll
        for (int mt = 0; mt < 2; mt++)
            #pragma unroll
            for (int nt = 0; nt < 4; nt++)
                #pragma unroll
                for (int i = 0; i < 4; i++) acc[mt][nt][i] = 0.f;

        {
            uint32_t aA = smem_u32(sA) + ((uint32_t)(wm + (lane & 15)) * SA_STRIDE + (lane >> 4) * 8) * 2;
            uint32_t bB = smem_u32(sB) + ((uint32_t)(wn + (lane & 7)) * SA_STRIDE + ((lane >> 3) & 1) * 8) * 2;
            const uint32_t rstep = 16 * SA_STRIDE * 2;
            const uint32_t nstep = 8 * SA_STRIDE * 2;
            #pragma unroll
            for (int ks = 0; ks < 8; ks++) {
                uint32_t koff = (uint32_t)ks * 32;
                uint32_t a0[4], a1[4];
                ldsm_x4(a0, aA + koff);
                ldsm_x4(a1, aA + rstep + koff);
                uint32_t b[4][2];
                #pragma unroll
                for (int nt = 0; nt < 4; nt++)
                    ldsm_x2(b[nt], bB + (uint32_t)nt * nstep + koff);
                #pragma unroll
                for (int nt = 0; nt < 4; nt++) {
                    mma_f16(acc[0][nt], a0, b[nt]);
                    mma_f16(acc[1][nt], a1, b[nt]);
                }
            }
        }
        __syncthreads();

        // D staging in dedicated region
        {
            int g = lane >> 2, t2 = (lane & 3) * 2;
            #pragma unroll
            for (int mt = 0; mt < 2; mt++)
                #pragma unroll
                for (int nt = 0; nt < 4; nt++) {
                    int r0 = wm + mt * 16 + g, c0 = wn + nt * 8 + t2;
                    *(float2*)(sD + r0 * SD_STRIDE + c0)       = make_float2(acc[mt][nt][0], acc[mt][nt][1]);
                    *(float2*)(sD + (r0 + 8) * SD_STRIDE + c0) = make_float2(acc[mt][nt][2], acc[mt][nt][3]);
                }
        }
        __syncthreads();

        // epilogue: Y (fp16) write + fp32 red scatter
        {
            int row = tid & 127, q = tid >> 7;
            long e = e0 + row;
            int d = ld_idx(dstp, e);
            const float4* sp = (const float4*)(sD + row * SD_STRIDE + q * 32);
            __half* yrow = Yout + (size_t)e * H + q * 32;
            float* srow = Sout + (size_t)d * H + q * 32;
            #pragma unroll
            for (int i = 0; i < 8; i++) {
                float4 v = sp[i];
                __half2 ha = __floats2half2_rn(v.x, v.y);
                __half2 hb = __floats2half2_rn(v.z, v.w);
                *(uint2*)(yrow + i * 4) = make_uint2(*(uint32_t*)&ha, *(uint32_t*)&hb);
                red4(srow + i * 4, v);
            }
        }
        __syncthreads();
    }
}

// ------- combine1: h = relu(S[src] - Y[rev]) -> g_h (fp16, streaming) --------
__global__ __launch_bounds__(256) void combine1(const float* __restrict__ S,
                                                const __half* __restrict__ Yv,
                                                const void* __restrict__ src,
                                                const void* __restrict__ rev) {
    long g = (long)blockIdx.x * 256 + threadIdx.x;
    long e = g >> 5;
    if (e >= NE) return;
    int q = (int)(g & 31) * 4;
    int s = ld_idx(src, e);
    long r = ld_idx(rev, e);
    float4 sv = *(const float4*)(S + (size_t)s * H + q);
    float4 yv = ld_y4(Yv + (size_t)r * H + q);
    float4 h;
    h.x = fmaxf(sv.x - yv.x, 0.f);
    h.y = fmaxf(sv.y - yv.y, 0.f);
    h.z = fmaxf(sv.z - yv.z, 0.f);
    h.w = fmaxf(sv.w - yv.w, 0.f);
    __half2 p0 = __floats2half2_rn(h.x, h.y);
    __half2 p1 = __floats2half2_rn(h.z, h.w);
    *(uint2*)(g_h + (size_t)e * H + q) = make_uint2(*(uint32_t*)&p0, *(uint32_t*)&p1);
}

// ------- combine2: scatter relu(S[src] - Y[rev]) into S3[dst] ----------------
__global__ __launch_bounds__(256) void combine2(const float* __restrict__ S,
                                                const __half* __restrict__ Yv,
                                                const void* __restrict__ src,
                                                const void* __restrict__ rev,
                                                float* __restrict__ S3,
                                                const void* __restrict__ dst) {
    long g = (long)blockIdx.x * 256 + threadIdx.x;
    long e = g >> 5;
    if (e >= NE) return;
    int q = (int)(g & 31) * 4;
    int s = ld_idx(src, e);
    long r = ld_idx(rev, e);
    int d = ld_idx(dst, e);
    float4 sv = *(const float4*)(S + (size_t)s * H + q);
    float4 yv = ld_y4(Yv + (size_t)r * H + q);
    float4 h;
    h.x = fmaxf(sv.x - yv.x, 0.f);
    h.y = fmaxf(sv.y - yv.y, 0.f);
    h.z = fmaxf(sv.z - yv.z, 0.f);
    h.w = fmaxf(sv.w - yv.w, 0.f);
    red4(S3 + (size_t)d * H + q, h);
}

// ---------------- launcher ----------------
extern "C" void kernel_launch(void* const* d_in, const int* in_sizes, int n_in,
                              void* d_out, int out_size) {
    const float* atom = (const float*)d_in[0];
    const float* bond = (const float*)d_in[1];
    const float* Wi   = (const float*)d_in[2];
    const float* Wh   = (const float*)d_in[3];
    const float* Wo   = (const float*)d_in[4];
    const void*  src  = d_in[5];
    const void*  dst  = d_in[6];
    const void*  rev  = d_in[7];
    float* out = (float*)d_out;

    __half *h, *y1, *y2, *B, *W1, *W2, *A1, *A2;
    float *P, *S1, *S2, *S3;
    cudaGetSymbolAddress((void**)&h,  g_h);
    cudaGetSymbolAddress((void**)&B,  g_B);
    cudaGetSymbolAddress((void**)&W1, g_W1);
    cudaGetSymbolAddress((void**)&W2, g_W2);
    cudaGetSymbolAddress((void**)&A1, g_A1);
    cudaGetSymbolAddress((void**)&A2, g_A2);
    cudaGetSymbolAddress((void**)&y1, g_y1);
    cudaGetSymbolAddress((void**)&y2, g_y2);
    cudaGetSymbolAddress((void**)&P,  g_P);
    cudaGetSymbolAddress((void**)&S1, g_S1);
    cudaGetSymbolAddress((void**)&S2, g_S2);
    cudaGetSymbolAddress((void**)&S3, g_S3);

    const int smemN  = 2 * NGMAT * 2 + 128 * SD_STRIDE * 4;   // 77824 + 67584 = 145408 B
    const int smemE0 = 3 * BMAT * 2 + 128 * SD_STRIDE * 4;    // 104448 + 67584 = 172032 B
    cudaFuncSetAttribute(ngemm<144, false>, cudaFuncAttributeMaxDynamicSharedMemorySize, smemN);
    cudaFuncSetAttribute(ngemm<288, true>,  cudaFuncAttributeMaxDynamicSharedMemorySize, smemN);
    cudaFuncSetAttribute(egemm0, cudaFuncAttributeMaxDynamicSharedMemorySize, smemE0);

    // 1: prep (zeros + weights + atom panel + idx detect)
    prep_all<<<ZB + WB + CB + 1, 256>>>(Wi, Wh, Wo, atom, (const unsigned int*)src,
                                        (float4*)S1, (float4*)S2, (float4*)S3);
    // 2: P = atom @ Wa^T  (fp16 single-pass)
    ngemm<144, false><<<NGRID, 512, smemN>>>(A1, W1, P);
    // 3: h0 = relu(P[src] + bond @ WbT)  (fp16)
    init_edges<<<2048, 256>>>(bond, src);
    // 4: iter 1: Y1 = h0 @ Wh^T (single-pass fp16), scatter S1   (ncu capture slot)
    egemm0<<<EGRID, 512, smemE0>>>(h, (const uint4*)B, y1, S1, dst);
    // 5: h1 = relu(S1[src] - Y1[rev])  (fp16)
    combine1<<<NE * 32 / 256, 256>>>(S1, y1, src, rev);
    // 6: iter 2: Y2 = h1 @ Wh^T, scatter S2
    egemm0<<<EGRID, 512, smemE0>>>(h, (const uint4*)B, y2, S2, dst);
    // 7: scatter relu(S2[src] - Y2[rev]) into S3
    combine2<<<NE * 32 / 256, 256>>>(S2, y2, src, rev, S3, dst);
    // 8: [atom|S3] panel (fp16)
    cvt2<<<(int)(((long)NROWS_PAD * 288 + 511) / 512), 512>>>(atom, S3);
    // 9: out = relu([atom|S3] @ Wo^T)  (fp16 single-pass)
    ngemm<288, true><<<NGRID, 512, smemN>>>(A2, W2, out);
}

// round 14
// speedup vs baseline: 1.9320x; 1.0064x over previous
#include <cuda_runtime.h>
#include <cuda_fp16.h>
#include <cstdint>

#define NN 50000
#define NE 800000
#define AF 133
#define BF 14
#define H  128
#define SA_STRIDE 136
#define SD_STRIDE 132
#define BMAT (128 * SA_STRIDE)          // elems per 128x128 16-bit smem matrix
#define ETILE 128
#define TILES_PER_CTA 5
#define EGRID (NE / ETILE / TILES_PER_CTA)   // 1250

#define NGS  152
#define NGMAT (128 * NGS)
#define NROWS_PAD 50048
#define NGRID 391

// ---------------- scratch ----------------
__device__ __half g_h [(size_t)NE * H];            // edge hidden (fp16)
__device__ __half g_y1[(size_t)NE * H];            // Y (fp16)
__device__ __half g_y2[(size_t)NE * H];
__device__ float g_P [(size_t)NN * H];
__device__ float g_S1[(size_t)NN * H];
__device__ float g_S2[(size_t)NN * H];
__device__ float g_S3[(size_t)NN * H];
__device__ float g_WbT[BF * H];
__device__ __half g_B [H * H];                     // Wh (fp16)  [n][k]
__device__ __half g_W1[128 * 144];                 // Wa padded (fp16) [n][k]
__device__ __half g_W2[128 * 288];                 // Wo padded (fp16) [n][k]
__device__ __half g_A1[(size_t)NROWS_PAD * 144];   // atom panel (fp16)
__device__ __half g_A2[(size_t)NROWS_PAD * 288];   // [atom|S3] panel (fp16)
__device__ int   g_idx64;

// ---------------- helpers ----------------
__device__ __forceinline__ int ld_idx(const void* p, long i) {
    if (g_idx64) return (int)__ldg((const long long*)p + i);
    return __ldg((const int*)p + i);
}
__device__ __forceinline__ void red4(float* p, float4 v) {
    asm volatile("red.global.add.v4.f32 [%0], {%1,%2,%3,%4};"
                 :: "l"(p), "f"(v.x), "f"(v.y), "f"(v.z), "f"(v.w) : "memory");
}
__device__ __forceinline__ uint32_t smem_u32(const void* p) {
    uint32_t a;
    asm("{ .reg .u64 t; cvta.to.shared.u64 t, %1; cvt.u32.u64 %0, t; }" : "=r"(a) : "l"(p));
    return a;
}
__device__ __forceinline__ void cp_async16(uint32_t sdst, const void* gsrc) {
    asm volatile("cp.async.cg.shared.global [%0], [%1], 16;" :: "r"(sdst), "l"(gsrc) : "memory");
}
__device__ __forceinline__ void cp_commit() {
    asm volatile("cp.async.commit_group;" ::: "memory");
}
template<int N> __device__ __forceinline__ void cp_wait() {
    asm volatile("cp.async.wait_group %0;" :: "n"(N) : "memory");
}
__device__ __forceinline__ void ldsm_x4(uint32_t (&r)[4], uint32_t addr) {
    asm volatile("ldmatrix.sync.aligned.m8n8.x4.shared.b16 {%0,%1,%2,%3}, [%4];"
                 : "=r"(r[0]), "=r"(r[1]), "=r"(r[2]), "=r"(r[3]) : "r"(addr));
}
__device__ __forceinline__ void ldsm_x2(uint32_t (&r)[2], uint32_t addr) {
    asm volatile("ldmatrix.sync.aligned.m8n8.x2.shared.b16 {%0,%1}, [%2];"
                 : "=r"(r[0]), "=r"(r[1]) : "r"(addr));
}
__device__ __forceinline__ void mma_f16(float (&d)[4], const uint32_t (&a)[4], const uint32_t (&b)[2]) {
    asm volatile("mma.sync.aligned.m16n8k16.row.col.f32.f16.f16.f32 "
                 "{%0,%1,%2,%3}, {%4,%5,%6,%7}, {%8,%9}, {%0,%1,%2,%3};"
                 : "+f"(d[0]), "+f"(d[1]), "+f"(d[2]), "+f"(d[3])
                 : "r"(a[0]), "r"(a[1]), "r"(a[2]), "r"(a[3]), "r"(b[0]), "r"(b[1]));
}
__device__ __forceinline__ float4 ld_y4(const __half* p) {
    uint2 raw = __ldg((const uint2*)p);
    __half2 h01 = *(__half2*)&raw.x;
    __half2 h23 = *(__half2*)&raw.y;
    float2 f01 = __half22float2(h01);
    float2 f23 = __half22float2(h23);
    return make_float4(f01.x, f01.y, f23.x, f23.y);
}

// ======= prep_all: zero S bufs | weight prep | atom panel | idx detect ======
#define ZB 18750
#define WB 144
#define CB 28152
__global__ __launch_bounds__(256) void prep_all(
    const float* __restrict__ Wi, const float* __restrict__ Wh,
    const float* __restrict__ Wo, const float* __restrict__ atom,
    const unsigned int* __restrict__ srcw,
    float4* __restrict__ S1, float4* __restrict__ S2, float4* __restrict__ S3)
{
    int b = blockIdx.x;
    if (b < ZB) {
        const long n = (long)NN * H / 4;
        long i = (long)b * 256 + threadIdx.x;
        float4 z = make_float4(0.f, 0.f, 0.f, 0.f);
        if (i < n) S1[i] = z;
        else if (i < 2 * n) S2[i - n] = z;
        else S3[i - 2 * n] = z;
        return;
    }
    b -= ZB;
    if (b < WB) {
        int i = b * 256 + threadIdx.x;
        if (i >= 128 * 288) return;
        if (i < BF * H) {
            int j = i & 127, k = i >> 7;
            g_WbT[i] = Wi[j * (AF + BF) + AF + k];
        }
        if (i < H * H)
            g_B[i] = __float2half_rn(Wh[i]);
        if (i < 128 * 144) {
            int n = i / 144, k = i % 144;
            g_W1[i] = __float2half_rn((k < AF) ? Wi[n * (AF + BF) + k] : 0.f);
        }
        {
            int n = i / 288, k = i % 288;
            g_W2[i] = __float2half_rn((k < AF + H) ? Wo[n * (AF + H) + k] : 0.f);
        }
        return;
    }
    b -= WB;
    if (b < CB) {
        long i = (long)b * 256 + threadIdx.x;
        int r = (int)(i / 144), c = (int)(i % 144);
        float v = (r < NN && c < AF) ? __ldg(atom + (size_t)r * AF + c) : 0.f;
        g_A1[i] = __float2half_rn(v);
        return;
    }
    __shared__ unsigned int s;
    if (threadIdx.x == 0) s = 0;
    __syncthreads();
    unsigned int v = srcw[threadIdx.x * 2 + 1] | srcw[2048 + threadIdx.x * 2 + 1];
    atomicOr(&s, v);
    __syncthreads();
    if (threadIdx.x == 0) g_idx64 = (s == 0u) ? 1 : 0;
}

// ---------------- cvt2: [atom|S3] panel (fp16) ----------------
__global__ void cvt2(const float* __restrict__ atom, const float* __restrict__ S3) {
    long i = (long)blockIdx.x * blockDim.x + threadIdx.x;
    if (i >= (long)NROWS_PAD * 288) return;
    int r = (int)(i / 288), c = (int)(i % 288);
    float v = 0.f;
    if (r < NN) {
        if (c < AF) v = __ldg(atom + (size_t)r * AF + c);
        else if (c < AF + H) v = __ldg(S3 + (size_t)r * H + (c - AF));
    }
    g_A2[i] = __float2half_rn(v);
}

// ---------------- node GEMM via mma.sync (single fp16, 1 pass) ---------------
template<int KPAD, bool RELU>
__global__ __launch_bounds__(512, 1) void ngemm(
    const __half* __restrict__ Ag, const __half* __restrict__ Wg,
    float* __restrict__ out)
{
    extern __shared__ __align__(16) char dyn[];
    __half* sB = (__half*)dyn;
    __half* sA = sB + NGMAT;
    float*  sD = (float*)(sA + NGMAT);   // dedicated staging

    int tid = threadIdx.x, lane = tid & 31, wid = tid >> 5;
    int m0 = blockIdx.x * 128;
    int wm = (wid >> 2) * 32, wn = (wid & 3) * 32;

    float acc[2][4][4];
    #pragma unroll
    for (int mt = 0; mt < 2; mt++)
        #pragma unroll
        for (int nt = 0; nt < 4; nt++)
            #pragma unroll
            for (int i = 0; i < 4; i++) acc[mt][nt][i] = 0.f;

    const int NCH = KPAD / 144;
    #pragma unroll
    for (int ch = 0; ch < NCH; ch++) {
        if (ch) __syncthreads();
        for (int i = tid; i < 128 * 18; i += 512) {
            int r = i / 18, c = i % 18;
            int go = r * KPAD + ch * 144 + c * 8;
            *(uint4*)(sB + r * NGS + c * 8) = *(const uint4*)(Wg + go);
        }
        for (int i = tid; i < 128 * 18; i += 512) {
            int r = i / 18, c = i % 18;
            size_t go = (size_t)(m0 + r) * KPAD + ch * 144 + c * 8;
            *(uint4*)(sA + r * NGS + c * 8) = *(const uint4*)(Ag + go);
        }
        __syncthreads();

        uint32_t aAddr0 = smem_u32(sA) + ((uint32_t)(wm + (lane & 15)) * NGS + (lane >> 4) * 8) * 2;
        uint32_t aAddr1 = aAddr0 + 16 * NGS * 2;
        uint32_t bAddr  = smem_u32(sB) + ((uint32_t)(wn + (lane & 7)) * NGS + ((lane >> 3) & 1) * 8) * 2;
        #pragma unroll
        for (int ks = 0; ks < 9; ks++) {
            uint32_t koff = (uint32_t)ks * 32;
            uint32_t a0[4], a1[4];
            ldsm_x4(a0, aAddr0 + koff);
            ldsm_x4(a1, aAddr1 + koff);
            uint32_t b[4][2];
            #pragma unroll
            for (int nt = 0; nt < 4; nt++)
                ldsm_x2(b[nt], bAddr + (uint32_t)nt * 8 * NGS * 2 + koff);
            #pragma unroll
            for (int nt = 0; nt < 4; nt++) {
                mma_f16(acc[0][nt], a0, b[nt]);
                mma_f16(acc[1][nt], a1, b[nt]);
            }
        }
    }
    __syncthreads();

    {
        int g = lane >> 2, t2 = (lane & 3) * 2;
        #pragma unroll
        for (int mt = 0; mt < 2; mt++)
            #pragma unroll
            for (int nt = 0; nt < 4; nt++) {
                int r0 = wm + mt * 16 + g, c0 = wn + nt * 8 + t2;
                float2 v0 = make_float2(acc[mt][nt][0], acc[mt][nt][1]);
                float2 v1 = make_float2(acc[mt][nt][2], acc[mt][nt][3]);
                if (RELU) {
                    v0.x = fmaxf(v0.x, 0.f); v0.y = fmaxf(v0.y, 0.f);
                    v1.x = fmaxf(v1.x, 0.f); v1.y = fmaxf(v1.y, 0.f);
                }
                *(float2*)(sD + r0 * SD_STRIDE + c0)       = v0;
                *(float2*)(sD + (r0 + 8) * SD_STRIDE + c0) = v1;
            }
    }
    __syncthreads();
    {
        int row = tid & 127, q = tid >> 7;
        if (m0 + row < NN) {
            const float4* sp = (const float4*)(sD + row * SD_STRIDE + q * 32);
            float* orow = out + (size_t)(m0 + row) * H + q * 32;
            #pragma unroll
            for (int i = 0; i < 8; i++) *(float4*)(orow + i * 4) = sp[i];
        }
    }
}

// ---- initial edge layer: h0 = relu(P[src] + bond @ WbT) (fp16) -------------
__global__ __launch_bounds__(256) void init_edges(const float* __restrict__ bond,
                                                  const void* __restrict__ src) {
    __shared__ float sWb[BF * H];
    for (int i = threadIdx.x; i < BF * H; i += 256) sWb[i] = g_WbT[i];
    __syncthreads();
    int warp = threadIdx.x >> 5, lane = threadIdx.x & 31;
    for (long e0 = (long)blockIdx.x * 8; e0 < NE; e0 += (long)gridDim.x * 8) {
        long e = e0 + warp;
        int s = ld_idx(src, e);
        int q = lane * 4;
        float4 acc = *(const float4*)(g_P + (size_t)s * H + q);
        const float* br = bond + e * BF;
        #pragma unroll
        for (int k = 0; k < BF; k++) {
            float b = __ldg(br + k);
            float4 w = *(const float4*)(sWb + k * H + q);
            acc.x += b * w.x; acc.y += b * w.y; acc.z += b * w.z; acc.w += b * w.w;
        }
        acc.x = fmaxf(acc.x, 0.f); acc.y = fmaxf(acc.y, 0.f);
        acc.z = fmaxf(acc.z, 0.f); acc.w = fmaxf(acc.w, 0.f);
        __half2 p0 = __floats2half2_rn(acc.x, acc.y);
        __half2 p1 = __floats2half2_rn(acc.z, acc.w);
        *(uint2*)(g_h + (size_t)e * H + q) = make_uint2(*(uint32_t*)&p0, *(uint32_t*)&p1);
    }
}

// ---------------- edge GEMM: streaming fp16 A, B fragments in registers ------
// smem: B | A stage0 | A stage1 | D staging (dedicated).
// B (Wh) is tile-invariant: each warp hoists its full B fragment set
// (8 ksteps x 4 ntiles x 2 regs = 64 regs) before the tile loop. Mainloop is
// then 2 LDSM + 8 mma per kstep.
__global__ __launch_bounds__(512, 1) void egemm0(
    const __half* __restrict__ Ag,
    const uint4* __restrict__ B4,
    __half* __restrict__ Yout, float* __restrict__ Sout,
    const void* __restrict__ dstp)
{
    extern __shared__ __align__(16) char dyn[];
    __half* sB = (__half*)dyn;
    __half* sSt0 = sB + BMAT;
    __half* sSt1 = sSt0 + BMAT;
    float* sD = (float*)(sSt1 + BMAT);   // dedicated fp32 staging

    int tid = threadIdx.x, lane = tid & 31, wid = tid >> 5;
    long tile0 = (long)blockIdx.x * TILES_PER_CTA;

    // prefetch tile 0
    {
        uint32_t st = smem_u32(sSt0);
        long e0 = tile0 * ETILE;
        #pragma unroll
        for (int it = 0; it < 4; it++) {
            int i = tid + it * 512;
            int r = i >> 4, c = i & 15;
            cp_async16(st + (uint32_t)(r * SA_STRIDE + c * 8) * 2,
                       Ag + (size_t)(e0 + r) * H + c * 8);
        }
        cp_commit();
    }

    // B resident in smem
    #pragma unroll
    for (int it = 0; it < 4; it++) {
        int i = tid + it * 512;
        int r = i >> 4, c = i & 15;
        *(uint4*)(sB + r * SA_STRIDE + c * 8) = __ldg(B4 + i);
    }
    __syncthreads();

    int wm = (wid >> 2) * 32;
    int wn = (wid & 3) * 32;

    // hoist B fragments into registers (once per CTA)
    uint32_t bfr[8][4][2];
    {
        uint32_t bB = smem_u32(sB) + ((uint32_t)(wn + (lane & 7)) * SA_STRIDE + ((lane >> 3) & 1) * 8) * 2;
        const uint32_t nstep = 8 * SA_STRIDE * 2;
        #pragma unroll
        for (int ks = 0; ks < 8; ks++)
            #pragma unroll
            for (int nt = 0; nt < 4; nt++)
                ldsm_x2(bfr[ks][nt], bB + (uint32_t)nt * nstep + (uint32_t)ks * 32);
    }

    for (int t = 0; t < TILES_PER_CTA; t++) {
        long e0 = (tile0 + t) * ETILE;
        __half* sA = (t & 1) ? sSt1 : sSt0;

        // issue prefetch(t+1) FIRST, then drain tile t
        if (t + 1 < TILES_PER_CTA) {
            __half* nx = (t & 1) ? sSt0 : sSt1;
            uint32_t st = smem_u32(nx);
            long en = (tile0 + t + 1) * ETILE;
            #pragma unroll
            for (int it = 0; it < 4; it++) {
                int i = tid + it * 512;
                int r = i >> 4, c = i & 15;
                cp_async16(st + (uint32_t)(r * SA_STRIDE + c * 8) * 2,
                           Ag + (size_t)(en + r) * H + c * 8);
            }
            cp_commit();
            cp_wait<1>();
        } else {
            cp_wait<0>();
        }
        __syncthreads();

        float acc[2][4][4];
        #pragma unroll
        for (int mt = 0; mt < 2; mt++)
            #pragma unroll
            for (int nt = 0; nt < 4; nt++)
                #pragma unroll
                for (int i = 0; i < 4; i++) acc[mt][nt][i] = 0.f;

        {
            uint32_t aA = smem_u32(sA) + ((uint32_t)(wm + (lane & 15)) * SA_STRIDE + (lane >> 4) * 8) * 2;
            const uint32_t rstep = 16 * SA_STRIDE * 2;
            #pragma unroll
            for (int ks = 0; ks < 8; ks++) {
                uint32_t koff = (uint32_t)ks * 32;
                uint32_t a0[4], a1[4];
                ldsm_x4(a0, aA + koff);
                ldsm_x4(a1, aA + rstep + koff);
                #pragma unroll
                for (int nt = 0; nt < 4; nt++) {
                    mma_f16(acc[0][nt], a0, bfr[ks][nt]);
                    mma_f16(acc[1][nt], a1, bfr[ks][nt]);
                }
            }
        }
        __syncthreads();

        // D staging in dedicated region
        {
            int g = lane >> 2, t2 = (lane & 3) * 2;
            #pragma unroll
            for (int mt = 0; mt < 2; mt++)
                #pragma unroll
                for (int nt = 0; nt < 4; nt++) {
                    int r0 = wm + mt * 16 + g, c0 = wn + nt * 8 + t2;
                    *(float2*)(sD + r0 * SD_STRIDE + c0)       = make_float2(acc[mt][nt][0], acc[mt][nt][1]);
                    *(float2*)(sD + (r0 + 8) * SD_STRIDE + c0) = make_float2(acc[mt][nt][2], acc[mt][nt][3]);
                }
        }
        __syncthreads();

        // epilogue: Y (fp16) write + fp32 red scatter
        {
            int row = tid & 127, q = tid >> 7;
            long e = e0 + row;
            int d = ld_idx(dstp, e);
            const float4* sp = (const float4*)(sD + row * SD_STRIDE + q * 32);
            __half* yrow = Yout + (size_t)e * H + q * 32;
            float* srow = Sout + (size_t)d * H + q * 32;
            #pragma unroll
            for (int i = 0; i < 8; i++) {
                float4 v = sp[i];
                __half2 ha = __floats2half2_rn(v.x, v.y);
                __half2 hb = __floats2half2_rn(v.z, v.w);
                *(uint2*)(yrow + i * 4) = make_uint2(*(uint32_t*)&ha, *(uint32_t*)&hb);
                red4(srow + i * 4, v);
            }
        }
        __syncthreads();
    }
}

// ------- combine1: h = relu(S[src] - Y[rev]) -> g_h (fp16, streaming) --------
__global__ __launch_bounds__(256) void combine1(const float* __restrict__ S,
                                                const __half* __restrict__ Yv,
                                                const void* __restrict__ src,
                                                const void* __restrict__ rev) {
    long g = (long)blockIdx.x * 256 + threadIdx.x;
    long e = g >> 5;
    if (e >= NE) return;
    int q = (int)(g & 31) * 4;
    int s = ld_idx(src, e);
    long r = ld_idx(rev, e);
    float4 sv = *(const float4*)(S + (size_t)s * H + q);
    float4 yv = ld_y4(Yv + (size_t)r * H + q);
    float4 h;
    h.x = fmaxf(sv.x - yv.x, 0.f);
    h.y = fmaxf(sv.y - yv.y, 0.f);
    h.z = fmaxf(sv.z - yv.z, 0.f);
    h.w = fmaxf(sv.w - yv.w, 0.f);
    __half2 p0 = __floats2half2_rn(h.x, h.y);
    __half2 p1 = __floats2half2_rn(h.z, h.w);
    *(uint2*)(g_h + (size_t)e * H + q) = make_uint2(*(uint32_t*)&p0, *(uint32_t*)&p1);
}

// ------- combine2: scatter relu(S[src] - Y[rev]) into S3[dst] ----------------
__global__ __launch_bounds__(256) void combine2(const float* __restrict__ S,
                                                const __half* __restrict__ Yv,
                                                const void* __restrict__ src,
                                                const void* __restrict__ rev,
                                                float* __restrict__ S3,
                                                const void* __restrict__ dst) {
    long g = (long)blockIdx.x * 256 + threadIdx.x;
    long e = g >> 5;
    if (e >= NE) return;
    int q = (int)(g & 31) * 4;
    int s = ld_idx(src, e);
    long r = ld_idx(rev, e);
    int d = ld_idx(dst, e);
    float4 sv = *(const float4*)(S + (size_t)s * H + q);
    float4 yv = ld_y4(Yv + (size_t)r * H + q);
    float4 h;
    h.x = fmaxf(sv.x - yv.x, 0.f);
    h.y = fmaxf(sv.y - yv.y, 0.f);
    h.z = fmaxf(sv.z - yv.z, 0.f);
    h.w = fmaxf(sv.w - yv.w, 0.f);
    red4(S3 + (size_t)d * H + q, h);
}

// ---------------- launcher ----------------
extern "C" void kernel_launch(void* const* d_in, const int* in_sizes, int n_in,
                              void* d_out, int out_size) {
    const float* atom = (const float*)d_in[0];
    const float* bond = (const float*)d_in[1];
    const float* Wi   = (const float*)d_in[2];
    const float* Wh   = (const float*)d_in[3];
    const float* Wo   = (const float*)d_in[4];
    const void*  src  = d_in[5];
    const void*  dst  = d_in[6];
    const void*  rev  = d_in[7];
    float* out = (float*)d_out;

    __half *h, *y1, *y2, *B, *W1, *W2, *A1, *A2;
    float *P, *S1, *S2, *S3;
    cudaGetSymbolAddress((void**)&h,  g_h);
    cudaGetSymbolAddress((void**)&B,  g_B);
    cudaGetSymbolAddress((void**)&W1, g_W1);
    cudaGetSymbolAddress((void**)&W2, g_W2);
    cudaGetSymbolAddress((void**)&A1, g_A1);
    cudaGetSymbolAddress((void**)&A2, g_A2);
    cudaGetSymbolAddress((void**)&y1, g_y1);
    cudaGetSymbolAddress((void**)&y2, g_y2);
    cudaGetSymbolAddress((void**)&P,  g_P);
    cudaGetSymbolAddress((void**)&S1, g_S1);
    cudaGetSymbolAddress((void**)&S2, g_S2);
    cudaGetSymbolAddress((void**)&S3, g_S3);

    const int smemN  = 2 * NGMAT * 2 + 128 * SD_STRIDE * 4;   // 145408 B
    const int smemE0 = 3 * BMAT * 2 + 128 * SD_STRIDE * 4;    // 172032 B
    cudaFuncSetAttribute(ngemm<144, false>, cudaFuncAttributeMaxDynamicSharedMemorySize, smemN);
    cudaFuncSetAttribute(ngemm<288, true>,  cudaFuncAttributeMaxDynamicSharedMemorySize, smemN);
    cudaFuncSetAttribute(egemm0, cudaFuncAttributeMaxDynamicSharedMemorySize, smemE0);

    // 1: prep (zeros + weights + atom panel + idx detect)
    prep_all<<<ZB + WB + CB + 1, 256>>>(Wi, Wh, Wo, atom, (const unsigned int*)src,
                                        (float4*)S1, (float4*)S2, (float4*)S3);
    // 2: P = atom @ Wa^T  (fp16 single-pass)
    ngemm<144, false><<<NGRID, 512, smemN>>>(A1, W1, P);
    // 3: h0 = relu(P[src] + bond @ WbT)  (fp16)
    init_edges<<<2048, 256>>>(bond, src);
    // 4: iter 1: Y1 = h0 @ Wh^T (B-in-regs), scatter S1   (ncu capture slot)
    egemm0<<<EGRID, 512, smemE0>>>(h, (const uint4*)B, y1, S1, dst);
    // 5: h1 = relu(S1[src] - Y1[rev])  (fp16)
    combine1<<<NE * 32 / 256, 256>>>(S1, y1, src, rev);
    // 6: iter 2: Y2 = h1 @ Wh^T, scatter S2
    egemm0<<<EGRID, 512, smemE0>>>(h, (const uint4*)B, y2, S2, dst);
    // 7: scatter relu(S2[src] - Y2[rev]) into S3
    combine2<<<NE * 32 / 256, 256>>>(S2, y2, src, rev, S3, dst);
    // 8: [atom|S3] panel (fp16)
    cvt2<<<(int)(((long)NROWS_PAD * 288 + 511) / 512), 512>>>(atom, S3);
    // 9: out = relu([atom|S3] @ Wo^T)  (fp16 single-pass)
    ngemm<288, true><<<NGRID, 512, smemN>>>(A2, W2, out);
}